// round 7
// baseline (speedup 1.0000x reference)
#include <cuda_runtime.h>

typedef unsigned long long u64;

#define TPB 128

// ---------- packed f32x2 helpers (sm_103a) ----------
__device__ __forceinline__ void fma2(u64 &d, u64 a, u64 b) {
    asm("fma.rn.f32x2 %0, %1, %2, %0;" : "+l"(d) : "l"(a), "l"(b));
}
__device__ __forceinline__ float unpack_add(u64 v) {
    float lo, hi;
    asm("mov.b64 {%0,%1}, %2;" : "=f"(lo), "=f"(hi) : "l"(v));
    return lo + hi;
}

// ---------- transposed positional tables (filled by pre-kernel) ----------
__device__ float g_posT_inner[8 * 64 * 64];
__device__ float g_posT_color[8 * 32 * 32];

__global__ void transpose_pos_kernel(const float* __restrict__ pos_inner,
                                     const float* __restrict__ pos_color)
{
    int t = blockIdx.x * blockDim.x + threadIdx.x;
    if (t < 8 * 64 * 64) {
        int h = t >> 12, i = (t >> 6) & 63, j = t & 63;   // src (h,i,j)
        g_posT_inner[(h << 12) | (j << 6) | i] = pos_inner[t];
    }
    if (t < 8 * 32 * 32) {
        int h = t >> 10, i = (t >> 5) & 31, j = t & 31;
        g_posT_color[(h << 10) | (j << 5) | i] = pos_color[t];
    }
}

// ---------- shared memory layout (floats). 2 windows -> 128 activation rows ----
#define LD64 68
#define LD32 36
#define OFF_X    0                      // 128x68: xf -> cat -> v2(scaled)
#define OFF_V1   8704                   // 128x68: v1 -> inner-out -> final
#define OFF_P    17408                  // 128x36: pan -> q1c
#define OFF_PQ   22016                  // 128x36: pan_q (until cos)
#define OFF_PK   26624                  // 128x36: pan_k
#define OFF_K1   31232                  // 128x36: k1c -> k2
#define OFF_WA   35840                  // 64x68 weight ping
#define OFF_WB   40192                  // 64x68 weight pong
#define OFF_COS  44544                  // 2*512
#define SMEM_FLOATS 45568               // 182272 B -> 1 CTA/SM

// async weight prefetch: W[NO][KA] row-major global -> padded smem (pitch KA+4)
template<int NO, int KA>
__device__ __forceinline__ void pfW(const float* __restrict__ g, float* __restrict__ s, int tid) {
    constexpr int LDW = KA + 4;
    constexpr int SH  = (KA == 64) ? 6 : 5;
    constexpr int CH  = (NO * KA) / (4 * TPB);   // 16B chunks per thread
    #pragma unroll
    for (int r = 0; r < CH; ++r) {
        int q = (tid + r * TPB) * 4;             // element index
        int o = q >> SH, k = q & (KA - 1);
        unsigned sa = (unsigned)__cvta_generic_to_shared(s + o * LDW + k);
        asm volatile("cp.async.ca.shared.global [%0], [%1], 16;\n" :: "r"(sa), "l"(g + q));
    }
    asm volatile("cp.async.commit_group;\n");
}
#define CP_WAIT1() asm volatile("cp.async.wait_group 1;\n")
#define CP_WAIT0() asm volatile("cp.async.wait_group 0;\n")

// O[128][NO] = A[128][KA] @ W[NO][KA]^T, 128 threads, thread tile 8 rows x (NO/8) cols
// cols strided by 8 (conflict-free W reads at pitch==4 mod 32); k packed in f32x2 pairs.
template<int NO, int KA, int LDA_, int LDO_>
__device__ __forceinline__ void gemm(const float* __restrict__ A, const float* __restrict__ W,
                                     float* __restrict__ O, int tid)
{
    constexpr int LDW = KA + 4;
    constexpr int TC  = NO / 8;
    const int cg = tid & 7;
    const int r0 = (tid >> 3) * 8;

    u64 acc[8][TC];
    #pragma unroll
    for (int i = 0; i < 8; ++i)
        #pragma unroll
        for (int j = 0; j < TC; ++j) acc[i][j] = 0ull;

    #pragma unroll
    for (int k = 0; k < KA; k += 4) {
        ulonglong2 a[8];
        #pragma unroll
        for (int i = 0; i < 8; ++i)
            a[i] = *(const ulonglong2*)(A + (r0 + i) * LDA_ + k);
        #pragma unroll
        for (int j = 0; j < TC; ++j) {
            ulonglong2 w = *(const ulonglong2*)(W + (cg + 8 * j) * LDW + k);
            #pragma unroll
            for (int i = 0; i < 8; ++i) {
                fma2(acc[i][j], a[i].x, w.x);
                fma2(acc[i][j], a[i].y, w.y);
            }
        }
    }
    #pragma unroll
    for (int i = 0; i < 8; ++i)
        #pragma unroll
        for (int j = 0; j < TC; ++j)
            O[(r0 + i) * LDO_ + cg + 8 * j] = unpack_add(acc[i][j]);
}

__global__ void __launch_bounds__(TPB, 1)
in2ma_kernel(const float* __restrict__ x,        const float* __restrict__ pan,
             const float* __restrict__ Wpq,      const float* __restrict__ Wpk,
             const float* __restrict__ Wv1,      const float* __restrict__ Wv2,
             const float* __restrict__ Wk2,      const float* __restrict__ Wq1c,
             const float* __restrict__ Wk1c,     const float* __restrict__ Wio,
             const float* __restrict__ Wto,      float* __restrict__ out)
{
    extern __shared__ float sm[];
    const int tid = threadIdx.x;
    const int gw  = blockIdx.x * 2;          // first window of the pair
    const int b   = gw >> 10;
    const int hi  = (gw >> 5) & 31;
    const int wi0 = gw & 31;                 // even; pair is wi0, wi0+1

    const int cb0 = (b * 64) * 65536 + (hi * 8) * 256 + wi0 * 8;
    const int pb0 = (b * 32) * 65536 + (hi * 8) * 256 + wi0 * 8;

    // prefetch first two weights while staging activations
    pfW<32, 32>(Wpq, sm + OFF_WA, tid);      // group 0
    pfW<32, 32>(Wpk, sm + OFF_WB, tid);      // group 1

    // ---- stage 2 windows: xf[128tok][64ch], pan[128tok][32ch] ----
    #pragma unroll 4
    for (int r = 0; r < 64; ++r) {
        int e = tid + r * TPB;
        int w = e >> 12, c = (e >> 6) & 63, t = e & 63;
        sm[OFF_X + (w * 64 + t) * LD64 + c] =
            x[cb0 + w * 8 + c * 65536 + (t >> 3) * 256 + (t & 7)];
    }
    #pragma unroll 4
    for (int r = 0; r < 32; ++r) {
        int e = tid + r * TPB;
        int w = e >> 11, c = (e >> 6) & 31, t = e & 63;
        sm[OFF_P + (w * 64 + t) * LD32 + c] =
            pan[pb0 + w * 8 + c * 65536 + (t >> 3) * 256 + (t & 7)];
    }

    // ---- gemm0: pan_q = P @ Wpq^T ----
    CP_WAIT1(); __syncthreads();
    gemm<32, 32, LD32, LD32>(sm + OFF_P, sm + OFF_WA, sm + OFF_PQ, tid);
    __syncthreads();
    pfW<64, 64>(Wv1, sm + OFF_WA, tid);      // group 2

    // ---- gemm1: pan_k = P @ Wpk^T ----
    CP_WAIT1(); __syncthreads();
    gemm<32, 32, LD32, LD32>(sm + OFF_P, sm + OFF_WB, sm + OFF_PK, tid);
    __syncthreads();
    pfW<32, 64>(Wq1c, sm + OFF_WB, tid);     // group 3

    // ---- gemm2: v1 = X @ Wv1^T ----
    CP_WAIT1(); __syncthreads();
    gemm<64, 64, LD64, LD64>(sm + OFF_X, sm + OFF_WA, sm + OFF_V1, tid);
    __syncthreads();
    pfW<32, 64>(Wk1c, sm + OFF_WA, tid);     // group 4

    // ---- gemm3: q1c = X @ Wq1c^T -> P (P dead) ----
    CP_WAIT1(); __syncthreads();
    gemm<32, 64, LD64, LD32>(sm + OFF_X, sm + OFF_WB, sm + OFF_P, tid);
    __syncthreads();
    pfW<64, 64>(Wio, sm + OFF_WB, tid);      // group 5

    // ---- gemm4: k1c = X @ Wk1c^T -> K1 ----
    CP_WAIT1(); __syncthreads();
    gemm<32, 64, LD64, LD32>(sm + OFF_X, sm + OFF_WA, sm + OFF_K1, tid);
    __syncthreads();
    pfW<64, 64>(Wv2, sm + OFF_WA, tid);      // group 6

    const float scale = 0.35355339059327373f;   // 8^-0.5

    // ---- pan window attention (2 windows): heads=8, dhead=4, seq=64 ----
    #pragma unroll
    for (int it = 0; it < 8; ++it) {
        int rr = tid + it * TPB;                 // (w, h, i)
        int w = rr >> 9, h = (rr >> 6) & 7, i = rr & 63;
        int R = w * 64 + i;
        const float* q = sm + OFF_PQ + R * LD32 + h * 4;
        float q0 = q[0] * scale, q1 = q[1] * scale, q2 = q[2] * scale, q3 = q[3] * scale;
        const float* piT = g_posT_inner + (h << 12) + i;
        float l = 0.f, o0 = 0.f, o1 = 0.f, o2 = 0.f, o3 = 0.f;
        #pragma unroll 4
        for (int j = 0; j < 64; ++j) {
            float4 kk = *(const float4*)(sm + OFF_PK + (w * 64 + j) * LD32 + h * 4);
            float s = q0 * kk.x + q1 * kk.y + q2 * kk.z + q3 * kk.w + piT[j << 6];
            float e = __expf(s);
            l += e;
            float4 vv = *(const float4*)(sm + OFF_V1 + (w * 64 + j) * LD64 + h * 4);
            o0 += e * vv.x; o1 += e * vv.y; o2 += e * vv.z; o3 += e * vv.w;
        }
        float inv = 1.f / l;
        float* oc = sm + OFF_X + R * LD64 + h * 4;   // cat cols [0,32)
        oc[0] = o0 * inv; oc[1] = o1 * inv; oc[2] = o2 * inv; oc[3] = o3 * inv;
    }

    // ---- color attention (2 windows): heads=8, n=32 channels, d=8 tokens ----
    #pragma unroll
    for (int it = 0; it < 4; ++it) {
        int u = tid + it * TPB;                  // (w, h, i)
        int w = u >> 8, h = (u >> 5) & 7, i = u & 31;
        float qd[8];
        #pragma unroll
        for (int d = 0; d < 8; ++d)
            qd[d] = sm[OFF_P + (w * 64 + h * 8 + d) * LD32 + i] * scale;
        const float* pcT = g_posT_color + (h << 10) + i;
        float l = 0.f;
        float o[8] = {0.f, 0.f, 0.f, 0.f, 0.f, 0.f, 0.f, 0.f};
        #pragma unroll 4
        for (int j = 0; j < 32; ++j) {
            float s = pcT[j << 5];
            #pragma unroll
            for (int d = 0; d < 8; ++d)
                s += qd[d] * sm[OFF_K1 + (w * 64 + h * 8 + d) * LD32 + j];
            float e = __expf(s);
            l += e;
            #pragma unroll
            for (int d = 0; d < 8; ++d)
                o[d] += e * sm[OFF_V1 + (w * 64 + h * 8 + d) * LD64 + 32 + j];
        }
        float inv = 1.f / l;
        #pragma unroll
        for (int d = 0; d < 8; ++d)
            sm[OFF_X + (w * 64 + h * 8 + d) * LD64 + 32 + i] = o[d] * inv;  // cat cols [32,64)
    }

    // ---- gemm5: out = cat @ Wio^T -> V1 ----
    CP_WAIT1(); __syncthreads();
    gemm<64, 64, LD64, LD64>(sm + OFF_X, sm + OFF_WB, sm + OFF_V1, tid);
    __syncthreads();
    pfW<32, 64>(Wk2, sm + OFF_WB, tid);      // group 7

    // ---- gemm6: v2 = out @ Wv2^T -> X ----
    CP_WAIT1(); __syncthreads();
    gemm<64, 64, LD64, LD64>(sm + OFF_V1, sm + OFF_WA, sm + OFF_X, tid);
    __syncthreads();
    pfW<64, 64>(Wto, sm + OFF_WA, tid);      // group 8

    // ---- gemm7: k2 = out @ Wk2^T -> K1 ----
    CP_WAIT1(); __syncthreads();
    gemm<32, 64, LD64, LD32>(sm + OFF_V1, sm + OFF_WB, sm + OFF_K1, tid);
    __syncthreads();

    // ---- cosine gate per (w, head, token) ----
    #pragma unroll
    for (int it = 0; it < 8; ++it) {
        int u = tid + it * TPB;
        int w = u >> 9, h = (u >> 6) & 7, t = u & 63;
        int R = w * 64 + t;
        const float* q = sm + OFF_PQ + R * LD32 + h * 4;
        const float* k = sm + OFF_K1 + R * LD32 + h * 4;
        float dot = 0.f, qq = 0.f, kk = 0.f;
        #pragma unroll
        for (int d = 0; d < 4; ++d) {
            dot += q[d] * k[d];
            qq  += q[d] * q[d];
            kk  += k[d] * k[d];
        }
        sm[OFF_COS + w * 512 + h * 64 + t] = dot * rsqrtf(qq * kk);
    }
    __syncthreads();

    // ---- scale v2 in place: v2[w][t][c] *= cos[w][c>>3][t] ----
    #pragma unroll 4
    for (int r = 0; r < 64; ++r) {
        int e = tid + r * TPB;
        int w = e >> 12, t = (e >> 6) & 63, c = e & 63;
        sm[OFF_X + (w * 64 + t) * LD64 + c] *= sm[OFF_COS + w * 512 + (c >> 3) * 64 + t];
    }

    // ---- gemm8: final = (cos*v2) @ Wto^T -> V1 ----
    CP_WAIT0(); __syncthreads();
    gemm<64, 64, LD64, LD64>(sm + OFF_X, sm + OFF_WA, sm + OFF_V1, tid);
    __syncthreads();

    // ---- un-partition and store ----
    #pragma unroll 4
    for (int r = 0; r < 64; ++r) {
        int e = tid + r * TPB;
        int w = e >> 12, c = (e >> 6) & 63, t = e & 63;
        out[cb0 + w * 8 + c * 65536 + (t >> 3) * 256 + (t & 7)] =
            sm[OFF_V1 + (w * 64 + t) * LD64 + c];
    }
}

extern "C" void kernel_launch(void* const* d_in, const int* in_sizes, int n_in,
                              void* d_out, int out_size)
{
    (void)in_sizes; (void)n_in; (void)out_size;

    transpose_pos_kernel<<<128, 256>>>((const float*)d_in[11],   // pos_inner
                                       (const float*)d_in[12]);  // pos_color

    const size_t smem_bytes = SMEM_FLOATS * sizeof(float);       // 182272 B
    cudaFuncSetAttribute(in2ma_kernel, cudaFuncAttributeMaxDynamicSharedMemorySize,
                         (int)smem_bytes);
    in2ma_kernel<<<2048, TPB, smem_bytes>>>(
        (const float*)d_in[0],  // x
        (const float*)d_in[1],  // pan_feature
        (const float*)d_in[2],  // W_pan_q
        (const float*)d_in[3],  // W_pan_k
        (const float*)d_in[4],  // W_v1
        (const float*)d_in[5],  // W_v2
        (const float*)d_in[6],  // W_k2
        (const float*)d_in[7],  // W_q1c
        (const float*)d_in[8],  // W_k1c
        (const float*)d_in[9],  // W_inner_out
        (const float*)d_in[10], // W_inter_out
        (float*)d_out);
}

// round 8
// speedup vs baseline: 1.8080x; 1.8080x over previous
#include <cuda_runtime.h>

typedef unsigned long long u64;

#define TPB 128

// ---------- packed f32x2 helpers (sm_103a) ----------
__device__ __forceinline__ void fma2(u64 &d, u64 a, u64 b) {
    asm("fma.rn.f32x2 %0, %1, %2, %0;" : "+l"(d) : "l"(a), "l"(b));
}
__device__ __forceinline__ float unpack_add(u64 v) {
    float lo, hi;
    asm("mov.b64 {%0,%1}, %2;" : "=f"(lo), "=f"(hi) : "l"(v));
    return lo + hi;
}

// ---------- transposed positional tables (filled by pre-kernel) ----------
__device__ float g_posT_inner[8 * 64 * 64];
__device__ float g_posT_color[8 * 32 * 32];

__global__ void transpose_pos_kernel(const float* __restrict__ pos_inner,
                                     const float* __restrict__ pos_color)
{
    int t = blockIdx.x * blockDim.x + threadIdx.x;
    if (t < 8 * 64 * 64) {
        int h = t >> 12, i = (t >> 6) & 63, j = t & 63;   // src (h,i,j)
        g_posT_inner[(h << 12) | (j << 6) | i] = pos_inner[t];
    }
    if (t < 8 * 32 * 32) {
        int h = t >> 10, i = (t >> 5) & 31, j = t & 31;
        g_posT_color[(h << 10) | (j << 5) | i] = pos_color[t];
    }
}

// ---------- shared memory layout (floats), 1 window / CTA (2 CTAs per SM) ----
#define LD64 68
#define LD32 36
#define OFF_X    0                       // 64x68: xf -> cat -> v2(scaled)
#define OFF_P    (OFF_X + 64*LD64)       // 64x36: pan
#define OFF_PQ   (OFF_P + 64*LD32)       // 64x36: pan_q (kept until cos)
#define OFF_PK   (OFF_PQ + 64*LD32)      // 64x36: pan_k
#define OFF_V1   (OFF_PK + 64*LD32)      // 64x68: v1 -> inner-out -> final
#define OFF_Q1   (OFF_V1 + 64*LD64)      // 64x36: q1c
#define OFF_K1   (OFF_Q1 + 64*LD32)      // 64x36: k1c -> k2
#define OFF_WA   (OFF_K1 + 64*LD32)      // 64x68: weight ping
#define OFF_WB   (OFF_WA + 64*LD64)      // 64x68: weight pong  (replaces old single W)
#define OFF_COS  (OFF_WB + 64*LD64)      // 512:   cos[h][t]
#define SMEM_FLOATS (OFF_COS + 512)      // 29440 floats = 117760 B?  -- check below

// NOTE: OFF_WB adds 64*68 = 4352 floats vs the old layout; total = 25088 + 4352 = 29440
// floats = 117,760 B. Two CTAs would need 235 KB > 228 KB. Shrink: WB only needs
// 64x68 worst case, but gemm32x32 weights are 32x36. We instead overlap WB with
// nothing and shrink the budget by using LD64 pads of 4 -> keep as is but verify:
// 117,760 * 2 = 235,520 > 228 KB. NOT OK. Fix: pack WA/WB as 64x66 (pitch 66 breaks
// 16B alignment). Better fix: WB aliases OFF_COS region + extra; simplest correct fix:
// reduce activation pads. We keep correctness by using a dedicated smaller pitch for
// weights handled below via LDWP = KA + 4 (unchanged) but allocating WB over the last
// 4352 floats of... -- Simpler: cap at 2 CTAs by trimming X/V1 pitch to 66? breaks
// float4 alignment. FINAL CHOICE: keep one weight buffer of 64x68 plus a second of
// 32x68 (the schedule below guarantees the buffer loaded while a 64x64 gemm runs is
// always a 32-row weight or vice versa is NOT true). So: accept 1.84 CTAs -> NO.
//
// Real resolution (used below): WA = 64x68 (4352), WB = 64x68 but overlapped onto
// OFF_COS+512 tail is unsafe. Instead we simply drop the separate OFF_Q1 buffer:
// q1c can live in OFF_P after pan (pan dead once pan_q/pan_k computed). That frees
// 64*36 = 2304 floats. New total = 29440 - 2304 = 27136 floats = 108,544 B.
// Two CTAs = 217,088 B <= 228 KB. OK.

#undef OFF_Q1
#undef OFF_K1
#undef OFF_WA
#undef OFF_WB
#undef OFF_COS
#undef SMEM_FLOATS
#define OFF_Q1   OFF_P                   // q1c reuses pan buffer (pan dead by then)
#define OFF_K1   (OFF_V1 + 64*LD64)      // 64x36: k1c -> k2
#define OFF_WA   (OFF_K1 + 64*LD32)      // 64x68 weight ping
#define OFF_WB   (OFF_WA + 64*LD64)      // 64x68 weight pong
#define OFF_COS  (OFF_WB + 64*LD64)      // 512: cos[h][t]
#define SMEM_FLOATS (OFF_COS + 512)      // 27136 floats = 108544 B -> 2 CTAs/SM

// async weight prefetch: W[NO][KA] row-major global -> padded smem (pitch KA+4)
template<int NO, int KA>
__device__ __forceinline__ void pfW(const float* __restrict__ g, float* __restrict__ s, int tid) {
    constexpr int LDW = KA + 4;
    constexpr int SH  = (KA == 64) ? 6 : 5;
    constexpr int CH  = (NO * KA) / (4 * TPB);   // 16B chunks per thread
    #pragma unroll
    for (int r = 0; r < CH; ++r) {
        int q = (tid + r * TPB) * 4;             // element index
        int o = q >> SH, k = q & (KA - 1);
        unsigned sa = (unsigned)__cvta_generic_to_shared(s + o * LDW + k);
        asm volatile("cp.async.ca.shared.global [%0], [%1], 16;\n" :: "r"(sa), "l"(g + q));
    }
    asm volatile("cp.async.commit_group;\n");
}
#define CP_WAIT1() asm volatile("cp.async.wait_group 1;\n")
#define CP_WAIT0() asm volatile("cp.async.wait_group 0;\n")

// O[64][NO] = A[64][KA] @ W[NO][KA]^T.  128 threads, thread tile 8 rows x (NO/16) cols.
// rows: (tid>>4)*8 .. +8 ;  cols: (tid&15) + 16j (conflict-free W reads at pitch==4 mod 32)
template<int NO, int KA>
__device__ __forceinline__ void gemm(const float* __restrict__ A, const float* __restrict__ W,
                                     float* __restrict__ O, int tid)
{
    constexpr int LDA = KA + 4, LDW = KA + 4, LDO = NO + 4;
    constexpr int TC  = NO / 16;
    const int ot = tid & 15;
    const int r0 = (tid >> 4) * 8;

    u64 acc[8][TC];
    #pragma unroll
    for (int i = 0; i < 8; ++i)
        #pragma unroll
        for (int j = 0; j < TC; ++j) acc[i][j] = 0ull;

    #pragma unroll
    for (int k = 0; k < KA; k += 4) {
        ulonglong2 a[8];
        #pragma unroll
        for (int i = 0; i < 8; ++i)
            a[i] = *(const ulonglong2*)(A + (r0 + i) * LDA + k);
        #pragma unroll
        for (int j = 0; j < TC; ++j) {
            ulonglong2 w = *(const ulonglong2*)(W + (ot + 16 * j) * LDW + k);
            #pragma unroll
            for (int i = 0; i < 8; ++i) {
                fma2(acc[i][j], a[i].x, w.x);
                fma2(acc[i][j], a[i].y, w.y);
            }
        }
    }
    #pragma unroll
    for (int i = 0; i < 8; ++i)
        #pragma unroll
        for (int j = 0; j < TC; ++j)
            O[(r0 + i) * LDO + ot + 16 * j] = unpack_add(acc[i][j]);
}

__global__ void __launch_bounds__(TPB, 2)
in2ma_kernel(const float* __restrict__ x,        const float* __restrict__ pan,
             const float* __restrict__ Wpq,      const float* __restrict__ Wpk,
             const float* __restrict__ Wv1,      const float* __restrict__ Wv2,
             const float* __restrict__ Wk2,      const float* __restrict__ Wq1c,
             const float* __restrict__ Wk1c,     const float* __restrict__ Wio,
             const float* __restrict__ Wto,      float* __restrict__ out)
{
    extern __shared__ float sm[];
    const int tid = threadIdx.x;
    const int wb  = blockIdx.x;
    const int b   = wb >> 10;
    const int hi  = (wb >> 5) & 31;
    const int wi  = wb & 31;

    const int cbase = (b * 64) * 65536 + (hi * 8) * 256 + wi * 8;
    const int pbase = (b * 32) * 65536 + (hi * 8) * 256 + wi * 8;

    // prefetch first two weights while staging activations
    pfW<32, 32>(Wpq, sm + OFF_WA, tid);      // group 0
    pfW<32, 32>(Wpk, sm + OFF_WB, tid);      // group 1

    // ---- stage window: xf[64tok][64ch], pan[64tok][32ch] ----
    #pragma unroll 4
    for (int r = 0; r < 32; ++r) {
        int e = tid + r * TPB;
        int c = e >> 6, t = e & 63;
        sm[OFF_X + t * LD64 + c] = x[cbase + c * 65536 + (t >> 3) * 256 + (t & 7)];
    }
    #pragma unroll 4
    for (int r = 0; r < 16; ++r) {
        int e = tid + r * TPB;
        int c = e >> 6, t = e & 63;
        sm[OFF_P + t * LD32 + c] = pan[pbase + c * 65536 + (t >> 3) * 256 + (t & 7)];
    }

    // ---- gemm0: pan_q = P @ Wpq^T -> PQ ----
    CP_WAIT1(); __syncthreads();
    gemm<32, 32>(sm + OFF_P, sm + OFF_WA, sm + OFF_PQ, tid);
    __syncthreads();
    pfW<64, 64>(Wv1, sm + OFF_WA, tid);      // group 2

    // ---- gemm1: pan_k = P @ Wpk^T -> PK ----
    CP_WAIT1(); __syncthreads();
    gemm<32, 32>(sm + OFF_P, sm + OFF_WB, sm + OFF_PK, tid);
    __syncthreads();
    pfW<32, 64>(Wq1c, sm + OFF_WB, tid);     // group 3

    // ---- gemm2: v1 = X @ Wv1^T -> V1 ----
    CP_WAIT1(); __syncthreads();
    gemm<64, 64>(sm + OFF_X, sm + OFF_WA, sm + OFF_V1, tid);
    __syncthreads();
    pfW<32, 64>(Wk1c, sm + OFF_WA, tid);     // group 4

    // ---- gemm3: q1c = X @ Wq1c^T -> Q1 (aliases P; pan is dead) ----
    CP_WAIT1(); __syncthreads();
    gemm<32, 64>(sm + OFF_X, sm + OFF_WB, sm + OFF_Q1, tid);
    __syncthreads();
    pfW<64, 64>(Wio, sm + OFF_WB, tid);      // group 5

    // ---- gemm4: k1c = X @ Wk1c^T -> K1 ----
    CP_WAIT1(); __syncthreads();
    gemm<32, 64>(sm + OFF_X, sm + OFF_WA, sm + OFF_K1, tid);
    __syncthreads();
    pfW<64, 64>(Wv2, sm + OFF_WA, tid);      // group 6

    const float scale = 0.35355339059327373f;   // 8^-0.5

    // ---- pan window attention: heads=8, dhead=4, seq=64 (512 rows / 4 iters) ----
    #pragma unroll
    for (int it = 0; it < 4; ++it) {
        int rr = tid + it * TPB;
        int h = rr >> 6, i = rr & 63;
        const float* q = sm + OFF_PQ + i * LD32 + h * 4;
        float q0 = q[0] * scale, q1 = q[1] * scale, q2 = q[2] * scale, q3 = q[3] * scale;
        const float* piT = g_posT_inner + (h << 12) + i;
        float l = 0.f, o0 = 0.f, o1 = 0.f, o2 = 0.f, o3 = 0.f;
        #pragma unroll 4
        for (int j = 0; j < 64; ++j) {
            float4 kk = *(const float4*)(sm + OFF_PK + j * LD32 + h * 4);
            float s = q0 * kk.x + q1 * kk.y + q2 * kk.z + q3 * kk.w + piT[j << 6];
            float e = __expf(s);
            l += e;
            float4 vv = *(const float4*)(sm + OFF_V1 + j * LD64 + h * 4); // v1_pan cols 0..31
            o0 += e * vv.x; o1 += e * vv.y; o2 += e * vv.z; o3 += e * vv.w;
        }
        float inv = 1.f / l;
        float* oc = sm + OFF_X + i * LD64 + h * 4;   // cat cols [0,32)
        oc[0] = o0 * inv; oc[1] = o1 * inv; oc[2] = o2 * inv; oc[3] = o3 * inv;
    }

    // ---- color attention: heads=8, n=32 channels, d=8 tokens (256 rows / 2 iters) ----
    #pragma unroll
    for (int it = 0; it < 2; ++it) {
        int u = tid + it * TPB;
        int h = u >> 5, i = u & 31;
        float qd[8];
        #pragma unroll
        for (int d = 0; d < 8; ++d)
            qd[d] = sm[OFF_Q1 + (h * 8 + d) * LD32 + i] * scale;
        const float* pcT = g_posT_color + (h << 10) + i;
        float l = 0.f;
        float o[8] = {0.f, 0.f, 0.f, 0.f, 0.f, 0.f, 0.f, 0.f};
        #pragma unroll 4
        for (int j = 0; j < 32; ++j) {
            float s = pcT[j << 5];
            #pragma unroll
            for (int d = 0; d < 8; ++d)
                s += qd[d] * sm[OFF_K1 + (h * 8 + d) * LD32 + j];
            float e = __expf(s);
            l += e;
            #pragma unroll
            for (int d = 0; d < 8; ++d)
                o[d] += e * sm[OFF_V1 + (h * 8 + d) * LD64 + 32 + j]; // v1_color cols 32..63
        }
        float inv = 1.f / l;
        #pragma unroll
        for (int d = 0; d < 8; ++d)
            sm[OFF_X + (h * 8 + d) * LD64 + 32 + i] = o[d] * inv;    // cat cols [32,64)
    }

    // ---- gemm5: out = cat @ Wio^T -> V1 ----
    CP_WAIT1(); __syncthreads();
    gemm<64, 64>(sm + OFF_X, sm + OFF_WB, sm + OFF_V1, tid);
    __syncthreads();
    pfW<32, 64>(Wk2, sm + OFF_WB, tid);      // group 7

    // ---- gemm6: v2 = out @ Wv2^T -> X ----
    CP_WAIT1(); __syncthreads();
    gemm<64, 64>(sm + OFF_V1, sm + OFF_WA, sm + OFF_X, tid);
    __syncthreads();
    pfW<64, 64>(Wto, sm + OFF_WA, tid);      // group 8

    // ---- gemm7: k2 = out @ Wk2^T -> K1 ----
    CP_WAIT1(); __syncthreads();
    gemm<32, 64>(sm + OFF_V1, sm + OFF_WB, sm + OFF_K1, tid);
    __syncthreads();

    // ---- cosine gate per (head, token) (512 / 4 iters) ----
    #pragma unroll
    for (int it = 0; it < 4; ++it) {
        int u = tid + it * TPB;
        int h = u >> 6, t = u & 63;
        const float* q = sm + OFF_PQ + t * LD32 + h * 4;
        const float* k = sm + OFF_K1 + t * LD32 + h * 4;
        float dot = 0.f, qq = 0.f, kk = 0.f;
        #pragma unroll
        for (int d = 0; d < 4; ++d) {
            dot += q[d] * k[d];
            qq  += q[d] * q[d];
            kk  += k[d] * k[d];
        }
        sm[OFF_COS + h * 64 + t] = dot * rsqrtf(qq * kk);
    }
    __syncthreads();

    // ---- scale v2 in place: v2[t][c] *= cos[c>>3][t] ----
    #pragma unroll 4
    for (int r = 0; r < 32; ++r) {
        int e = tid + r * TPB;
        int t = e >> 6, c = e & 63;
        sm[OFF_X + t * LD64 + c] *= sm[OFF_COS + (c >> 3) * 64 + t];
    }

    // ---- gemm8: final = (cos*v2) @ Wto^T -> V1 ----
    CP_WAIT0(); __syncthreads();
    gemm<64, 64>(sm + OFF_X, sm + OFF_WA, sm + OFF_V1, tid);
    __syncthreads();

    // ---- un-partition and store ----
    #pragma unroll 4
    for (int r = 0; r < 32; ++r) {
        int e = tid + r * TPB;
        int c = e >> 6, t = e & 63;
        out[cbase + c * 65536 + (t >> 3) * 256 + (t & 7)] = sm[OFF_V1 + t * LD64 + c];
    }
}

extern "C" void kernel_launch(void* const* d_in, const int* in_sizes, int n_in,
                              void* d_out, int out_size)
{
    (void)in_sizes; (void)n_in; (void)out_size;

    transpose_pos_kernel<<<128, 256>>>((const float*)d_in[11],   // pos_inner
                                       (const float*)d_in[12]);  // pos_color

    const size_t smem_bytes = SMEM_FLOATS * sizeof(float);       // 108,544 B
    cudaFuncSetAttribute(in2ma_kernel, cudaFuncAttributeMaxDynamicSharedMemorySize,
                         (int)smem_bytes);
    in2ma_kernel<<<4096, TPB, smem_bytes>>>(
        (const float*)d_in[0],  // x
        (const float*)d_in[1],  // pan_feature
        (const float*)d_in[2],  // W_pan_q
        (const float*)d_in[3],  // W_pan_k
        (const float*)d_in[4],  // W_v1
        (const float*)d_in[5],  // W_v2
        (const float*)d_in[6],  // W_k2
        (const float*)d_in[7],  // W_q1c
        (const float*)d_in[8],  // W_k1c
        (const float*)d_in[9],  // W_inner_out
        (const float*)d_in[10], // W_inter_out
        (float*)d_out);
}

// round 10
// speedup vs baseline: 2.5511x; 1.4110x over previous
#include <cuda_runtime.h>

typedef unsigned long long u64;

#define TPB 256

// ---------- packed f32x2 helpers (sm_103a) ----------
__device__ __forceinline__ void fma2(u64 &d, u64 a, u64 b) {
    asm("fma.rn.f32x2 %0, %1, %2, %0;" : "+l"(d) : "l"(a), "l"(b));
}
__device__ __forceinline__ float unpack_add(u64 v) {
    float lo, hi;
    asm("mov.b64 {%0,%1}, %2;" : "=f"(lo), "=f"(hi) : "l"(v));
    return lo + hi;
}

// ---------- transposed positional tables (filled by pre-kernel) ----------
__device__ float g_posT_inner[8 * 64 * 64];
__device__ float g_posT_color[8 * 32 * 32];

__global__ void transpose_pos_kernel(const float* __restrict__ pos_inner,
                                     const float* __restrict__ pos_color)
{
    int t = blockIdx.x * blockDim.x + threadIdx.x;
    if (t < 8 * 64 * 64) {
        int h = t >> 12, i = (t >> 6) & 63, j = t & 63;   // src (h,i,j)
        g_posT_inner[(h << 12) | (j << 6) | i] = pos_inner[t];
    }
    if (t < 8 * 32 * 32) {
        int h = t >> 10, i = (t >> 5) & 31, j = t & 31;
        g_posT_color[(h << 10) | (j << 5) | i] = pos_color[t];
    }
}

// ---------- shared memory layout (floats), 1 window / CTA, 2 CTAs / SM ----
#define LD64 68
#define LD32 36
#define OFF_X    0                       // 64x68: xf -> cat -> v2(scaled)
#define OFF_P    (OFF_X + 64*LD64)       // 64x36: pan, later q1c (pan dead by then)
#define OFF_PQ   (OFF_P + 64*LD32)       // 64x36: pan_q (kept until cos)
#define OFF_PK   (OFF_PQ + 64*LD32)      // 64x36: pan_k
#define OFF_V1   (OFF_PK + 64*LD32)      // 64x68: v1 -> inner-out -> final
#define OFF_Q1   OFF_P                   // alias: q1c reuses pan buffer
#define OFF_K1   (OFF_V1 + 64*LD64)      // 64x36: k1c -> k2
#define OFF_WA   (OFF_K1 + 64*LD32)      // 64x68: weight ping
#define OFF_WB   (OFF_WA + 64*LD64)      // 64x68: weight pong
#define OFF_COS  (OFF_WB + 64*LD64)      // 512:   cos[h][t]
#define SMEM_FLOATS (OFF_COS + 512)      // 27136 floats = 108544 B -> 2 CTAs/SM

// async weight prefetch: W[NO][KA] row-major global -> padded smem (pitch KA+4)
template<int NO, int KA>
__device__ __forceinline__ void pfW(const float* __restrict__ g, float* __restrict__ s, int tid) {
    constexpr int LDW = KA + 4;
    constexpr int SH  = (KA == 64) ? 6 : 5;
    constexpr int CH  = (NO * KA) / (4 * TPB);   // 16B chunks per thread (>=1 for all shapes)
    #pragma unroll
    for (int r = 0; r < CH; ++r) {
        int q = (tid + r * TPB) * 4;             // element index
        int o = q >> SH, k = q & (KA - 1);
        unsigned sa = (unsigned)__cvta_generic_to_shared(s + o * LDW + k);
        asm volatile("cp.async.ca.shared.global [%0], [%1], 16;\n" :: "r"(sa), "l"(g + q));
    }
    asm volatile("cp.async.commit_group;\n");
}
#define CP_WAIT1() asm volatile("cp.async.wait_group 1;\n")
#define CP_WAIT0() asm volatile("cp.async.wait_group 0;\n")

// O[64][NO] = A[64][KA] @ W[NO][KA]^T   (all smem, padded pitches KA+4 / NO+4)
// 256 threads; thread tile = 4 tokens x TN outputs (outputs strided by 16).
// Exactly the R5 gemm (regs=128 @ launch_bounds(256,2), proven fastest shape).
template<int NO, int KA>
__device__ __forceinline__ void gemm(const float* __restrict__ A, const float* __restrict__ W,
                                     float* __restrict__ O, int tid)
{
    constexpr int LDA = KA + 4, LDW = KA + 4, LDO = NO + 4;
    constexpr int TN  = NO / 16;
    const int ot = tid & 15;
    const int t0 = (tid >> 4) * 4;

    u64 acc[4][TN];
    #pragma unroll
    for (int i = 0; i < 4; ++i)
        #pragma unroll
        for (int j = 0; j < TN; ++j) acc[i][j] = 0ull;

    #pragma unroll
    for (int k = 0; k < KA; k += 4) {
        ulonglong2 a[4], w[TN];
        #pragma unroll
        for (int i = 0; i < 4; ++i)
            a[i] = *(const ulonglong2*)(A + (t0 + i) * LDA + k);
        #pragma unroll
        for (int j = 0; j < TN; ++j)
            w[j] = *(const ulonglong2*)(W + (ot + 16 * j) * LDW + k);
        #pragma unroll
        for (int i = 0; i < 4; ++i)
            #pragma unroll
            for (int j = 0; j < TN; ++j) {
                fma2(acc[i][j], a[i].x, w[j].x);
                fma2(acc[i][j], a[i].y, w[j].y);
            }
    }
    #pragma unroll
    for (int i = 0; i < 4; ++i)
        #pragma unroll
        for (int j = 0; j < TN; ++j)
            O[(t0 + i) * LDO + ot + 16 * j] = unpack_add(acc[i][j]);
}

__global__ void __launch_bounds__(TPB, 2)
in2ma_kernel(const float* __restrict__ x,        const float* __restrict__ pan,
             const float* __restrict__ Wpq,      const float* __restrict__ Wpk,
             const float* __restrict__ Wv1,      const float* __restrict__ Wv2,
             const float* __restrict__ Wk2,      const float* __restrict__ Wq1c,
             const float* __restrict__ Wk1c,     const float* __restrict__ Wio,
             const float* __restrict__ Wto,      float* __restrict__ out)
{
    extern __shared__ float sm[];
    const int tid = threadIdx.x;
    const int wb  = blockIdx.x;
    const int b   = wb >> 10;
    const int hi  = (wb >> 5) & 31;
    const int wi  = wb & 31;

    const int cbase = (b * 64) * 65536 + (hi * 8) * 256 + wi * 8;
    const int pbase = (b * 32) * 65536 + (hi * 8) * 256 + wi * 8;

    // prefetch first two weights while staging activations
    pfW<32, 32>(Wpq, sm + OFF_WA, tid);      // group 0
    pfW<32, 32>(Wpk, sm + OFF_WB, tid);      // group 1

    // ---- stage window: xf[64tok][64ch], pan[64tok][32ch] ----
    #pragma unroll
    for (int r = 0; r < 16; ++r) {
        int e = tid + r * TPB;
        int c = e >> 6, t = e & 63;
        sm[OFF_X + t * LD64 + c] = x[cbase + c * 65536 + (t >> 3) * 256 + (t & 7)];
    }
    #pragma unroll
    for (int r = 0; r < 8; ++r) {
        int e = tid + r * TPB;
        int c = e >> 6, t = e & 63;
        sm[OFF_P + t * LD32 + c] = pan[pbase + c * 65536 + (t >> 3) * 256 + (t & 7)];
    }

    // ---- gemm0: pan_q = P @ Wpq^T -> PQ ----
    CP_WAIT1(); __syncthreads();
    gemm<32, 32>(sm + OFF_P, sm + OFF_WA, sm + OFF_PQ, tid);
    __syncthreads();
    pfW<64, 64>(Wv1, sm + OFF_WA, tid);      // group 2

    // ---- gemm1: pan_k = P @ Wpk^T -> PK ----
    CP_WAIT1(); __syncthreads();
    gemm<32, 32>(sm + OFF_P, sm + OFF_WB, sm + OFF_PK, tid);
    __syncthreads();
    pfW<32, 64>(Wq1c, sm + OFF_WB, tid);     // group 3

    // ---- gemm2: v1 = X @ Wv1^T -> V1 ----
    CP_WAIT1(); __syncthreads();
    gemm<64, 64>(sm + OFF_X, sm + OFF_WA, sm + OFF_V1, tid);
    __syncthreads();
    pfW<32, 64>(Wk1c, sm + OFF_WA, tid);     // group 4

    // ---- gemm3: q1c = X @ Wq1c^T -> Q1 (aliases P; pan is dead) ----
    CP_WAIT1(); __syncthreads();
    gemm<32, 64>(sm + OFF_X, sm + OFF_WB, sm + OFF_Q1, tid);
    __syncthreads();
    pfW<64, 64>(Wio, sm + OFF_WB, tid);      // group 5

    // ---- gemm4: k1c = X @ Wk1c^T -> K1 ----
    CP_WAIT1(); __syncthreads();
    gemm<32, 64>(sm + OFF_X, sm + OFF_WA, sm + OFF_K1, tid);
    __syncthreads();
    pfW<64, 64>(Wv2, sm + OFF_WA, tid);      // group 6

    const float scale = 0.35355339059327373f;   // 8^-0.5

    // ---- pan window attention: heads=8, dhead=4, seq=64 (512 rows / 2 iters) ----
    #pragma unroll
    for (int rr0 = 0; rr0 < 2; ++rr0) {
        int rr = tid + rr0 * TPB;
        int h = rr >> 6, i = rr & 63;
        const float* q = sm + OFF_PQ + i * LD32 + h * 4;
        float q0 = q[0] * scale, q1 = q[1] * scale, q2 = q[2] * scale, q3 = q[3] * scale;
        const float* piT = g_posT_inner + (h << 12) + i;
        float l = 0.f, o0 = 0.f, o1 = 0.f, o2 = 0.f, o3 = 0.f;
        #pragma unroll 4
        for (int j = 0; j < 64; ++j) {
            float4 kk = *(const float4*)(sm + OFF_PK + j * LD32 + h * 4);
            float s = q0 * kk.x + q1 * kk.y + q2 * kk.z + q3 * kk.w + piT[j << 6];
            float e = __expf(s);
            l += e;
            float4 vv = *(const float4*)(sm + OFF_V1 + j * LD64 + h * 4); // v1_pan cols 0..31
            o0 += e * vv.x; o1 += e * vv.y; o2 += e * vv.z; o3 += e * vv.w;
        }
        float inv = 1.f / l;
        float* oc = sm + OFF_X + i * LD64 + h * 4;   // cat cols [0,32)
        oc[0] = o0 * inv; oc[1] = o1 * inv; oc[2] = o2 * inv; oc[3] = o3 * inv;
    }

    // ---- color attention: heads=8, n=32 channels, d=8 tokens (256 rows / 1 iter) ----
    {
        int h = tid >> 5, i = tid & 31;
        float qd[8];
        #pragma unroll
        for (int d = 0; d < 8; ++d)
            qd[d] = sm[OFF_Q1 + (h * 8 + d) * LD32 + i] * scale;
        const float* pcT = g_posT_color + (h << 10) + i;
        float l = 0.f;
        float o[8] = {0.f, 0.f, 0.f, 0.f, 0.f, 0.f, 0.f, 0.f};
        #pragma unroll 4
        for (int j = 0; j < 32; ++j) {
            float s = pcT[j << 5];
            #pragma unroll
            for (int d = 0; d < 8; ++d)
                s += qd[d] * sm[OFF_K1 + (h * 8 + d) * LD32 + j];
            float e = __expf(s);
            l += e;
            #pragma unroll
            for (int d = 0; d < 8; ++d)
                o[d] += e * sm[OFF_V1 + (h * 8 + d) * LD64 + 32 + j]; // v1_color cols 32..63
        }
        float inv = 1.f / l;
        #pragma unroll
        for (int d = 0; d < 8; ++d)
            sm[OFF_X + (h * 8 + d) * LD64 + 32 + i] = o[d] * inv;    // cat cols [32,64)
    }

    // ---- gemm5: out = cat @ Wio^T -> V1 ----
    CP_WAIT1(); __syncthreads();
    gemm<64, 64>(sm + OFF_X, sm + OFF_WB, sm + OFF_V1, tid);
    __syncthreads();
    pfW<32, 64>(Wk2, sm + OFF_WB, tid);      // group 7

    // ---- gemm6: v2 = out @ Wv2^T -> X ----
    CP_WAIT1(); __syncthreads();
    gemm<64, 64>(sm + OFF_V1, sm + OFF_WA, sm + OFF_X, tid);
    __syncthreads();
    pfW<64, 64>(Wto, sm + OFF_WA, tid);      // group 8

    // ---- gemm7: k2 = out @ Wk2^T -> K1 ----
    CP_WAIT1(); __syncthreads();
    gemm<32, 64>(sm + OFF_V1, sm + OFF_WB, sm + OFF_K1, tid);
    __syncthreads();

    // ---- cosine gate per (head, token) (512 / 2 iters) ----
    #pragma unroll
    for (int rr0 = 0; rr0 < 2; ++rr0) {
        int u = tid + rr0 * TPB;
        int h = u >> 6, t = u & 63;
        const float* q = sm + OFF_PQ + t * LD32 + h * 4;
        const float* k = sm + OFF_K1 + t * LD32 + h * 4;
        float dot = 0.f, qq = 0.f, kk = 0.f;
        #pragma unroll
        for (int d = 0; d < 4; ++d) {
            dot += q[d] * k[d];
            qq  += q[d] * q[d];
            kk  += k[d] * k[d];
        }
        sm[OFF_COS + h * 64 + t] = dot * rsqrtf(qq * kk);
    }
    __syncthreads();

    // ---- scale v2 in place: v2[t][c] *= cos[c>>3][t] ----
    #pragma unroll
    for (int r = 0; r < 16; ++r) {
        int e = tid + r * TPB;
        int t = e >> 6, c = e & 63;
        sm[OFF_X + t * LD64 + c] *= sm[OFF_COS + (c >> 3) * 64 + t];
    }

    // ---- gemm8: final = (cos*v2) @ Wto^T -> V1 ----
    CP_WAIT0(); __syncthreads();
    gemm<64, 64>(sm + OFF_X, sm + OFF_WA, sm + OFF_V1, tid);
    __syncthreads();

    // ---- un-partition and store ----
    #pragma unroll
    for (int r = 0; r < 16; ++r) {
        int e = tid + r * TPB;
        int c = e >> 6, t = e & 63;
        out[cbase + c * 65536 + (t >> 3) * 256 + (t & 7)] = sm[OFF_V1 + t * LD64 + c];
    }
}

extern "C" void kernel_launch(void* const* d_in, const int* in_sizes, int n_in,
                              void* d_out, int out_size)
{
    (void)in_sizes; (void)n_in; (void)out_size;

    transpose_pos_kernel<<<128, 256>>>((const float*)d_in[11],   // pos_inner
                                       (const float*)d_in[12]);  // pos_color

    const size_t smem_bytes = SMEM_FLOATS * sizeof(float);       // 108,544 B
    cudaFuncSetAttribute(in2ma_kernel, cudaFuncAttributeMaxDynamicSharedMemorySize,
                         (int)smem_bytes);
    in2ma_kernel<<<4096, TPB, smem_bytes>>>(
        (const float*)d_in[0],  // x
        (const float*)d_in[1],  // pan_feature
        (const float*)d_in[2],  // W_pan_q
        (const float*)d_in[3],  // W_pan_k
        (const float*)d_in[4],  // W_v1
        (const float*)d_in[5],  // W_v2
        (const float*)d_in[6],  // W_k2
        (const float*)d_in[7],  // W_q1c
        (const float*)d_in[8],  // W_k1c
        (const float*)d_in[9],  // W_inner_out
        (const float*)d_in[10], // W_inter_out
        (float*)d_out);
}

// round 11
// speedup vs baseline: 2.5751x; 1.0094x over previous
#include <cuda_runtime.h>

typedef unsigned long long u64;

#define TPB 256

// ---------- packed f32x2 helpers (sm_103a) ----------
__device__ __forceinline__ void fma2(u64 &d, u64 a, u64 b) {
    asm("fma.rn.f32x2 %0, %1, %2, %0;" : "+l"(d) : "l"(a), "l"(b));
}
__device__ __forceinline__ float unpack_add(u64 v) {
    float lo, hi;
    asm("mov.b64 {%0,%1}, %2;" : "=f"(lo), "=f"(hi) : "l"(v));
    return lo + hi;
}

// ---------- transposed positional tables (filled by pre-kernel) ----------
__device__ float g_posT_inner[8 * 64 * 64];
__device__ float g_posT_color[8 * 32 * 32];

__global__ void transpose_pos_kernel(const float* __restrict__ pos_inner,
                                     const float* __restrict__ pos_color)
{
    int t = blockIdx.x * blockDim.x + threadIdx.x;
    if (t < 8 * 64 * 64) {
        int h = t >> 12, i = (t >> 6) & 63, j = t & 63;   // src (h,i,j)
        g_posT_inner[(h << 12) | (j << 6) | i] = pos_inner[t];
    }
    if (t < 8 * 32 * 32) {
        int h = t >> 10, i = (t >> 5) & 31, j = t & 31;
        g_posT_color[(h << 10) | (j << 5) | i] = pos_color[t];
    }
}

// ---------- shared memory layout (floats), 1 window / CTA, 2 CTAs / SM ----
#define LD64 68
#define LD32 36
#define OFF_X    0                       // 64x68: xf -> cat -> v2(scaled)
#define OFF_P    (OFF_X + 64*LD64)       // 64x36: pan, later q1c (pan dead by then)
#define OFF_PQ   (OFF_P + 64*LD32)       // 64x36: pan_q (kept until cos)
#define OFF_PK   (OFF_PQ + 64*LD32)      // 64x36: pan_k
#define OFF_V1   (OFF_PK + 64*LD32)      // 64x68: v1 -> inner-out -> final
#define OFF_Q1   OFF_P                   // alias: q1c reuses pan buffer
#define OFF_K1   (OFF_V1 + 64*LD64)      // 64x36: k1c -> k2
#define OFF_WA   (OFF_K1 + 64*LD32)      // 64x68: weight ping
#define OFF_WB   (OFF_WA + 64*LD64)      // 64x68: weight pong
#define OFF_COS  (OFF_WB + 64*LD64)      // 512:   cos[h][t]
#define SMEM_FLOATS (OFF_COS + 512)      // 27136 floats = 108544 B -> 2 CTAs/SM

// async weight prefetch: W[NO][KA] row-major global -> padded smem (pitch KA+4)
template<int NO, int KA>
__device__ __forceinline__ void pfW(const float* __restrict__ g, float* __restrict__ s, int tid) {
    constexpr int LDW = KA + 4;
    constexpr int SH  = (KA == 64) ? 6 : 5;
    constexpr int CH  = (NO * KA) / (4 * TPB);
    #pragma unroll
    for (int r = 0; r < CH; ++r) {
        int q = (tid + r * TPB) * 4;
        int o = q >> SH, k = q & (KA - 1);
        unsigned sa = (unsigned)__cvta_generic_to_shared(s + o * LDW + k);
        asm volatile("cp.async.ca.shared.global [%0], [%1], 16;\n" :: "r"(sa), "l"(g + q));
    }
    asm volatile("cp.async.commit_group;\n");
}
#define CP_WAIT1() asm volatile("cp.async.wait_group 1;\n")
#define CP_WAIT0() asm volatile("cp.async.wait_group 0;\n")

// O[64][NO] = A[64][KA] @ W[NO][KA]^T   (all smem, padded pitches KA+4 / NO+4)
// 256 threads, 8 warps. Warp tile: 16 rows x (NO/2) cols
//   (rb = wid>>1 row-block of 16; cb = wid&1 col-block of NO/2)
// Lane: rg = lane>>3 (4 row-groups of 4), cl = lane&7 (8 col lanes, cols strided 8).
// W LDS.128: 8 distinct rows * 16B = 128 B = 1 wavefront (conflict-free: row
// stride 68 or 36 == 4 mod 32 banks -> lanes tile all 32 banks).
// A LDS.128: phase-broadcast (quarter-warp shares address) = 1 wavefront.
template<int NO, int KA>
__device__ __forceinline__ void gemm(const float* __restrict__ A, const float* __restrict__ W,
                                     float* __restrict__ O, int tid)
{
    constexpr int LDA = KA + 4, LDW = KA + 4, LDO = NO + 4;
    constexpr int TN  = NO / 16;          // cols per thread (stride 8)
    constexpr int CB  = NO / 2;           // warp col-block width
    const int wid  = tid >> 5, lane = tid & 31;
    const int r0   = (wid >> 1) * 16 + (lane >> 3) * 4;
    const int c0   = (wid & 1) * CB + (lane & 7);

    u64 acc[4][TN];
    #pragma unroll
    for (int i = 0; i < 4; ++i)
        #pragma unroll
        for (int j = 0; j < TN; ++j) acc[i][j] = 0ull;

    #pragma unroll
    for (int k = 0; k < KA; k += 4) {
        ulonglong2 a[4], w[TN];
        #pragma unroll
        for (int i = 0; i < 4; ++i)
            a[i] = *(const ulonglong2*)(A + (r0 + i) * LDA + k);
        #pragma unroll
        for (int j = 0; j < TN; ++j)
            w[j] = *(const ulonglong2*)(W + (c0 + 8 * j) * LDW + k);
        #pragma unroll
        for (int i = 0; i < 4; ++i)
            #pragma unroll
            for (int j = 0; j < TN; ++j) {
                fma2(acc[i][j], a[i].x, w[j].x);
                fma2(acc[i][j], a[i].y, w[j].y);
            }
    }
    #pragma unroll
    for (int i = 0; i < 4; ++i)
        #pragma unroll
        for (int j = 0; j < TN; ++j)
            O[(r0 + i) * LDO + c0 + 8 * j] = unpack_add(acc[i][j]);
}

__global__ void __launch_bounds__(TPB, 2)
in2ma_kernel(const float* __restrict__ x,        const float* __restrict__ pan,
             const float* __restrict__ Wpq,      const float* __restrict__ Wpk,
             const float* __restrict__ Wv1,      const float* __restrict__ Wv2,
             const float* __restrict__ Wk2,      const float* __restrict__ Wq1c,
             const float* __restrict__ Wk1c,     const float* __restrict__ Wio,
             const float* __restrict__ Wto,      float* __restrict__ out)
{
    extern __shared__ float sm[];
    const int tid = threadIdx.x;
    const int wb  = blockIdx.x;
    const int b   = wb >> 10;
    const int hi  = (wb >> 5) & 31;
    const int wi  = wb & 31;

    const int cbase = (b * 64) * 65536 + (hi * 8) * 256 + wi * 8;
    const int pbase = (b * 32) * 65536 + (hi * 8) * 256 + wi * 8;

    // prefetch first two weights while staging activations
    pfW<32, 32>(Wpq, sm + OFF_WA, tid);      // group 0
    pfW<32, 32>(Wpk, sm + OFF_WB, tid);      // group 1

    // ---- stage window: xf[64tok][64ch], pan[64tok][32ch] ----
    #pragma unroll
    for (int r = 0; r < 16; ++r) {
        int e = tid + r * TPB;
        int c = e >> 6, t = e & 63;
        sm[OFF_X + t * LD64 + c] = x[cbase + c * 65536 + (t >> 3) * 256 + (t & 7)];
    }
    #pragma unroll
    for (int r = 0; r < 8; ++r) {
        int e = tid + r * TPB;
        int c = e >> 6, t = e & 63;
        sm[OFF_P + t * LD32 + c] = pan[pbase + c * 65536 + (t >> 3) * 256 + (t & 7)];
    }

    // ---- gemm0: pan_q = P @ Wpq^T -> PQ ----
    CP_WAIT1(); __syncthreads();
    gemm<32, 32>(sm + OFF_P, sm + OFF_WA, sm + OFF_PQ, tid);
    __syncthreads();
    pfW<64, 64>(Wv1, sm + OFF_WA, tid);      // group 2

    // ---- gemm1: pan_k = P @ Wpk^T -> PK ----
    CP_WAIT1(); __syncthreads();
    gemm<32, 32>(sm + OFF_P, sm + OFF_WB, sm + OFF_PK, tid);
    __syncthreads();
    pfW<32, 64>(Wq1c, sm + OFF_WB, tid);     // group 3

    // ---- gemm2: v1 = X @ Wv1^T -> V1 ----
    CP_WAIT1(); __syncthreads();
    gemm<64, 64>(sm + OFF_X, sm + OFF_WA, sm + OFF_V1, tid);
    __syncthreads();
    pfW<32, 64>(Wk1c, sm + OFF_WA, tid);     // group 4

    // ---- gemm3: q1c = X @ Wq1c^T -> Q1 (aliases P; pan is dead) ----
    CP_WAIT1(); __syncthreads();
    gemm<32, 64>(sm + OFF_X, sm + OFF_WB, sm + OFF_Q1, tid);
    __syncthreads();
    pfW<64, 64>(Wio, sm + OFF_WB, tid);      // group 5

    // ---- gemm4: k1c = X @ Wk1c^T -> K1 ----
    CP_WAIT1(); __syncthreads();
    gemm<32, 64>(sm + OFF_X, sm + OFF_WA, sm + OFF_K1, tid);
    __syncthreads();
    pfW<64, 64>(Wv2, sm + OFF_WA, tid);      // group 6

    const float scale = 0.35355339059327373f;   // 8^-0.5

    // ---- pan window attention: heads=8, dhead=4, seq=64 (512 rows / 2 iters) ----
    #pragma unroll
    for (int rr0 = 0; rr0 < 2; ++rr0) {
        int rr = tid + rr0 * TPB;
        int h = rr >> 6, i = rr & 63;
        const float* q = sm + OFF_PQ + i * LD32 + h * 4;
        float q0 = q[0] * scale, q1 = q[1] * scale, q2 = q[2] * scale, q3 = q[3] * scale;
        const float* piT = g_posT_inner + (h << 12) + i;
        float l = 0.f, o0 = 0.f, o1 = 0.f, o2 = 0.f, o3 = 0.f;
        #pragma unroll 4
        for (int j = 0; j < 64; ++j) {
            float4 kk = *(const float4*)(sm + OFF_PK + j * LD32 + h * 4);
            float s = q0 * kk.x + q1 * kk.y + q2 * kk.z + q3 * kk.w + piT[j << 6];
            float e = __expf(s);
            l += e;
            float4 vv = *(const float4*)(sm + OFF_V1 + j * LD64 + h * 4); // v1_pan cols 0..31
            o0 += e * vv.x; o1 += e * vv.y; o2 += e * vv.z; o3 += e * vv.w;
        }
        float inv = 1.f / l;
        float* oc = sm + OFF_X + i * LD64 + h * 4;   // cat cols [0,32)
        oc[0] = o0 * inv; oc[1] = o1 * inv; oc[2] = o2 * inv; oc[3] = o3 * inv;
    }

    // ---- color attention: heads=8, n=32 channels, d=8 tokens ----
    // Two-phase with score registers; K1/V read as float4 broadcasts
    // (8x8 LDS.128 each instead of 256 scalar LDS: 512 -> 128 wavefronts).
    {
        int h = tid >> 5, i = tid & 31;
        float qd[8];
        #pragma unroll
        for (int d = 0; d < 8; ++d)
            qd[d] = sm[OFF_Q1 + (h * 8 + d) * LD32 + i] * scale;
        const float* pcT = g_posT_color + (h << 10) + i;
        float s[32];
        #pragma unroll
        for (int j = 0; j < 32; ++j)
            s[j] = pcT[j << 5];
        #pragma unroll
        for (int d = 0; d < 8; ++d) {
            const float* kr = sm + OFF_K1 + (h * 8 + d) * LD32;
            #pragma unroll
            for (int jc = 0; jc < 8; ++jc) {
                float4 k4 = *(const float4*)(kr + jc * 4);
                s[jc * 4 + 0] += qd[d] * k4.x;
                s[jc * 4 + 1] += qd[d] * k4.y;
                s[jc * 4 + 2] += qd[d] * k4.z;
                s[jc * 4 + 3] += qd[d] * k4.w;
            }
        }
        float l = 0.f;
        #pragma unroll
        for (int j = 0; j < 32; ++j) {
            s[j] = __expf(s[j]);
            l += s[j];
        }
        float o[8] = {0.f, 0.f, 0.f, 0.f, 0.f, 0.f, 0.f, 0.f};
        #pragma unroll
        for (int d = 0; d < 8; ++d) {
            const float* vr = sm + OFF_V1 + (h * 8 + d) * LD64 + 32;   // v1_color cols
            #pragma unroll
            for (int jc = 0; jc < 8; ++jc) {
                float4 v4 = *(const float4*)(vr + jc * 4);
                o[d] += s[jc * 4 + 0] * v4.x + s[jc * 4 + 1] * v4.y
                      + s[jc * 4 + 2] * v4.z + s[jc * 4 + 3] * v4.w;
            }
        }
        float inv = 1.f / l;
        #pragma unroll
        for (int d = 0; d < 8; ++d)
            sm[OFF_X + (h * 8 + d) * LD64 + 32 + i] = o[d] * inv;   // cat cols [32,64)
    }

    // ---- gemm5: out = cat @ Wio^T -> V1 ----
    CP_WAIT1(); __syncthreads();
    gemm<64, 64>(sm + OFF_X, sm + OFF_WB, sm + OFF_V1, tid);
    __syncthreads();
    pfW<32, 64>(Wk2, sm + OFF_WB, tid);      // group 7

    // ---- gemm6: v2 = out @ Wv2^T -> X ----
    CP_WAIT1(); __syncthreads();
    gemm<64, 64>(sm + OFF_V1, sm + OFF_WA, sm + OFF_X, tid);
    __syncthreads();
    pfW<64, 64>(Wto, sm + OFF_WA, tid);      // group 8

    // ---- gemm7: k2 = out @ Wk2^T -> K1 ----
    CP_WAIT1(); __syncthreads();
    gemm<32, 64>(sm + OFF_V1, sm + OFF_WB, sm + OFF_K1, tid);
    __syncthreads();

    // ---- cosine gate per (head, token) (512 / 2 iters) ----
    #pragma unroll
    for (int rr0 = 0; rr0 < 2; ++rr0) {
        int u = tid + rr0 * TPB;
        int h = u >> 6, t = u & 63;
        const float* q = sm + OFF_PQ + t * LD32 + h * 4;
        const float* k = sm + OFF_K1 + t * LD32 + h * 4;
        float dot = 0.f, qq = 0.f, kk = 0.f;
        #pragma unroll
        for (int d = 0; d < 4; ++d) {
            dot += q[d] * k[d];
            qq  += q[d] * q[d];
            kk  += k[d] * k[d];
        }
        sm[OFF_COS + h * 64 + t] = dot * rsqrtf(qq * kk);
    }
    __syncthreads();

    // ---- scale v2 in place: v2[t][c] *= cos[c>>3][t] ----
    #pragma unroll
    for (int r = 0; r < 16; ++r) {
        int e = tid + r * TPB;
        int t = e >> 6, c = e & 63;
        sm[OFF_X + t * LD64 + c] *= sm[OFF_COS + (c >> 3) * 64 + t];
    }

    // ---- gemm8: final = (cos*v2) @ Wto^T -> V1 ----
    CP_WAIT0(); __syncthreads();
    gemm<64, 64>(sm + OFF_X, sm + OFF_WA, sm + OFF_V1, tid);
    __syncthreads();

    // ---- un-partition and store ----
    #pragma unroll
    for (int r = 0; r < 16; ++r) {
        int e = tid + r * TPB;
        int c = e >> 6, t = e & 63;
        out[cbase + c * 65536 + (t >> 3) * 256 + (t & 7)] = sm[OFF_V1 + t * LD64 + c];
    }
}

extern "C" void kernel_launch(void* const* d_in, const int* in_sizes, int n_in,
                              void* d_out, int out_size)
{
    (void)in_sizes; (void)n_in; (void)out_size;

    transpose_pos_kernel<<<128, 256>>>((const float*)d_in[11],   // pos_inner
                                       (const float*)d_in[12]);  // pos_color

    const size_t smem_bytes = SMEM_FLOATS * sizeof(float);       // 108,544 B
    cudaFuncSetAttribute(in2ma_kernel, cudaFuncAttributeMaxDynamicSharedMemorySize,
                         (int)smem_bytes);
    in2ma_kernel<<<4096, TPB, smem_bytes>>>(
        (const float*)d_in[0],  // x
        (const float*)d_in[1],  // pan_feature
        (const float*)d_in[2],  // W_pan_q
        (const float*)d_in[3],  // W_pan_k
        (const float*)d_in[4],  // W_v1
        (const float*)d_in[5],  // W_v2
        (const float*)d_in[6],  // W_k2
        (const float*)d_in[7],  // W_q1c
        (const float*)d_in[8],  // W_k1c
        (const float*)d_in[9],  // W_inner_out
        (const float*)d_in[10], // W_inter_out
        (float*)d_out);
}

// round 14
// speedup vs baseline: 3.5104x; 1.3632x over previous
#include <cuda_runtime.h>

typedef unsigned long long u64;

#define TPB 256

// ---------- tf32 helpers ----------
__device__ __forceinline__ unsigned cvt_tf32(float v) {
    unsigned r;
    asm("cvt.rna.tf32.f32 %0, %1;" : "=r"(r) : "f"(v));
    return r;
}
__device__ __forceinline__ float tf32_round(float v) {
    return __uint_as_float(cvt_tf32(v));
}
__device__ __forceinline__ void mma_tf32(float* c, const unsigned* a, const unsigned* b) {
    asm volatile(
        "mma.sync.aligned.m16n8k8.row.col.f32.tf32.tf32.f32 "
        "{%0,%1,%2,%3}, {%4,%5,%6,%7}, {%8,%9}, {%0,%1,%2,%3};"
        : "+f"(c[0]), "+f"(c[1]), "+f"(c[2]), "+f"(c[3])
        : "r"(a[0]), "r"(a[1]), "r"(a[2]), "r"(a[3]), "r"(b[0]), "r"(b[1]));
}

// ---------- device scratch: transposed pos tables + tf32-rounded weights ----------
__device__ float g_posT_inner[8 * 64 * 64];
__device__ float g_posT_color[8 * 32 * 32];
__device__ float g_Wpq [32 * 32];
__device__ float g_Wpk [32 * 32];
__device__ float g_Wv1 [64 * 64];
__device__ float g_Wv2 [64 * 64];
__device__ float g_Wk2 [32 * 64];
__device__ float g_Wq1c[32 * 64];
__device__ float g_Wk1c[32 * 64];
__device__ float g_Wio [64 * 64];
__device__ float g_Wto [64 * 64];

__global__ void prep_kernel(const float* __restrict__ pos_inner,
                            const float* __restrict__ pos_color,
                            const float* __restrict__ Wpq,  const float* __restrict__ Wpk,
                            const float* __restrict__ Wv1,  const float* __restrict__ Wv2,
                            const float* __restrict__ Wk2,  const float* __restrict__ Wq1c,
                            const float* __restrict__ Wk1c, const float* __restrict__ Wio,
                            const float* __restrict__ Wto)
{
    int t = blockIdx.x * blockDim.x + threadIdx.x;
    if (t < 8 * 64 * 64) {
        int h = t >> 12, i = (t >> 6) & 63, j = t & 63;   // src (h,i,j)
        g_posT_inner[(h << 12) | (j << 6) | i] = pos_inner[t];
    }
    if (t < 8 * 32 * 32) {
        int h = t >> 10, i = (t >> 5) & 31, j = t & 31;
        g_posT_color[(h << 10) | (j << 5) | i] = pos_color[t];
    }
    if (t < 1024) { g_Wpq[t] = tf32_round(Wpq[t]); g_Wpk[t] = tf32_round(Wpk[t]); }
    if (t < 2048) {
        g_Wk2[t]  = tf32_round(Wk2[t]);
        g_Wq1c[t] = tf32_round(Wq1c[t]);
        g_Wk1c[t] = tf32_round(Wk1c[t]);
    }
    if (t < 4096) {
        g_Wv1[t] = tf32_round(Wv1[t]);
        g_Wv2[t] = tf32_round(Wv2[t]);
        g_Wio[t] = tf32_round(Wio[t]);
        g_Wto[t] = tf32_round(Wto[t]);
    }
}

// ---------- shared memory layout (floats), 1 window / CTA, 2 CTAs / SM ----
#define LD64 68
#define LD32 36
#define OFF_X    0                       // 64x68: xf -> cat -> v2(scaled)
#define OFF_P    (OFF_X + 64*LD64)       // 64x36: pan, later q1c (pan dead by then)
#define OFF_PQ   (OFF_P + 64*LD32)       // 64x36: pan_q (kept until cos)
#define OFF_PK   (OFF_PQ + 64*LD32)      // 64x36: pan_k
#define OFF_V1   (OFF_PK + 64*LD32)      // 64x68: v1 -> inner-out -> final
#define OFF_Q1   OFF_P                   // alias: q1c reuses pan buffer
#define OFF_K1   (OFF_V1 + 64*LD64)      // 64x36: k1c -> k2
#define OFF_WA   (OFF_K1 + 64*LD32)      // 64x68: weight ping
#define OFF_WB   (OFF_WA + 64*LD64)      // 64x68: weight pong
#define OFF_COS  (OFF_WB + 64*LD64)      // 512:   cos[h][t]
#define SMEM_FLOATS (OFF_COS + 512)      // 27136 floats = 108544 B -> 2 CTAs/SM

// async weight prefetch: W[NO][KA] row-major (pre-rounded scratch) -> padded smem
template<int NO, int KA>
__device__ __forceinline__ void pfW(const float* __restrict__ g, float* __restrict__ s, int tid) {
    constexpr int LDW = KA + 4;
    constexpr int SH  = (KA == 64) ? 6 : 5;
    constexpr int CH  = (NO * KA) / (4 * TPB);
    #pragma unroll
    for (int r = 0; r < CH; ++r) {
        int q = (tid + r * TPB) * 4;
        int o = q >> SH, k = q & (KA - 1);
        unsigned sa = (unsigned)__cvta_generic_to_shared(s + o * LDW + k);
        asm volatile("cp.async.ca.shared.global [%0], [%1], 16;\n" :: "r"(sa), "l"(g + q));
    }
    asm volatile("cp.async.commit_group;\n");
}
#define CP_WAIT1() asm volatile("cp.async.wait_group 1;\n")
#define CP_WAIT0() asm volatile("cp.async.wait_group 0;\n")

// O[64][NO] = A[64][KA] @ W[NO][KA]^T  via split-A 2-term tf32 mma (fp32 accum).
// A = A_hi + A_lo (each tf32): acc += A_hi*B + A_lo*B. W is ALREADY tf32-rounded
// (pre-rounded in prep_kernel), so B fragments load with no cvt and the only
// residual error is B's single tf32 rounding.
// 8 warps: warp (wid&3) owns M-rows [(wid&3)*16,+16); (wid>>2) owns N-half.
template<int NO, int KA>
__device__ __forceinline__ void gemm(const float* __restrict__ A, const float* __restrict__ W,
                                     float* __restrict__ O, int tid)
{
    constexpr int LDA = KA + 4, LDW = KA + 4, LDO = NO + 4;
    constexpr int NB  = NO / 16;
    const int wid  = tid >> 5, lane = tid & 31;
    const int m0   = (wid & 3) * 16;
    const int n0   = (wid >> 2) * (NO / 2);
    const int gr   = lane >> 2, tg = lane & 3;

    float acc[NB][4];
    #pragma unroll
    for (int nb = 0; nb < NB; ++nb)
        #pragma unroll
        for (int q = 0; q < 4; ++q) acc[nb][q] = 0.f;

    const float* Ar0 = A + (m0 + gr) * LDA + tg;
    const float* Ar1 = A + (m0 + 8 + gr) * LDA + tg;

    #pragma unroll
    for (int kb = 0; kb < KA / 8; ++kb) {
        const int k0 = kb * 8;
        float av[4];
        av[0] = Ar0[k0];
        av[1] = Ar1[k0];
        av[2] = Ar0[k0 + 4];
        av[3] = Ar1[k0 + 4];
        unsigned ahi[4], alo[4];
        #pragma unroll
        for (int q = 0; q < 4; ++q) {
            ahi[q] = cvt_tf32(av[q]);
            float lo = av[q] - __uint_as_float(ahi[q]);
            alo[q] = cvt_tf32(lo);
        }
        #pragma unroll
        for (int nb = 0; nb < NB; ++nb) {
            const float* wr = W + (n0 + nb * 8 + gr) * LDW + k0 + tg;
            unsigned b[2];
            b[0] = __float_as_uint(wr[0]);
            b[1] = __float_as_uint(wr[4]);
            mma_tf32(acc[nb], ahi, b);
            mma_tf32(acc[nb], alo, b);
        }
    }
    #pragma unroll
    for (int nb = 0; nb < NB; ++nb) {
        float* o0 = O + (m0 + gr) * LDO + n0 + nb * 8 + tg * 2;
        float* o1 = O + (m0 + 8 + gr) * LDO + n0 + nb * 8 + tg * 2;
        *(float2*)o0 = make_float2(acc[nb][0], acc[nb][1]);
        *(float2*)o1 = make_float2(acc[nb][2], acc[nb][3]);
    }
}

__global__ void __launch_bounds__(TPB, 2)
in2ma_kernel(const float* __restrict__ x, const float* __restrict__ pan,
             float* __restrict__ out)
{
    extern __shared__ float sm[];
    const int tid = threadIdx.x;
    const int wb  = blockIdx.x;
    const int b   = wb >> 10;
    const int hi  = (wb >> 5) & 31;
    const int wi  = wb & 31;

    const int cbase = (b * 64) * 65536 + (hi * 8) * 256 + wi * 8;
    const int pbase = (b * 32) * 65536 + (hi * 8) * 256 + wi * 8;

    // prefetch first two weights while staging activations
    pfW<32, 32>(g_Wpq, sm + OFF_WA, tid);    // group 0
    pfW<32, 32>(g_Wpk, sm + OFF_WB, tid);    // group 1

    // ---- stage window: xf[64tok][64ch], pan[64tok][32ch] ----
    #pragma unroll
    for (int r = 0; r < 16; ++r) {
        int e = tid + r * TPB;
        int c = e >> 6, t = e & 63;
        sm[OFF_X + t * LD64 + c] = x[cbase + c * 65536 + (t >> 3) * 256 + (t & 7)];
    }
    #pragma unroll
    for (int r = 0; r < 8; ++r) {
        int e = tid + r * TPB;
        int c = e >> 6, t = e & 63;
        sm[OFF_P + t * LD32 + c] = pan[pbase + c * 65536 + (t >> 3) * 256 + (t & 7)];
    }

    // ---- gemm0: pan_q = P @ Wpq^T -> PQ ----
    CP_WAIT1(); __syncthreads();
    gemm<32, 32>(sm + OFF_P, sm + OFF_WA, sm + OFF_PQ, tid);
    __syncthreads();
    pfW<64, 64>(g_Wv1, sm + OFF_WA, tid);    // group 2

    // ---- gemm1: pan_k = P @ Wpk^T -> PK ----
    CP_WAIT1(); __syncthreads();
    gemm<32, 32>(sm + OFF_P, sm + OFF_WB, sm + OFF_PK, tid);
    __syncthreads();
    pfW<32, 64>(g_Wq1c, sm + OFF_WB, tid);   // group 3

    // ---- gemm2: v1 = X @ Wv1^T -> V1 ----
    CP_WAIT1(); __syncthreads();
    gemm<64, 64>(sm + OFF_X, sm + OFF_WA, sm + OFF_V1, tid);
    __syncthreads();
    pfW<32, 64>(g_Wk1c, sm + OFF_WA, tid);   // group 4

    // ---- gemm3: q1c = X @ Wq1c^T -> Q1 (aliases P; pan is dead) ----
    CP_WAIT1(); __syncthreads();
    gemm<32, 64>(sm + OFF_X, sm + OFF_WB, sm + OFF_Q1, tid);
    __syncthreads();
    pfW<64, 64>(g_Wio, sm + OFF_WB, tid);    // group 5

    // ---- gemm4: k1c = X @ Wk1c^T -> K1 ----
    CP_WAIT1(); __syncthreads();
    gemm<32, 64>(sm + OFF_X, sm + OFF_WA, sm + OFF_K1, tid);
    __syncthreads();
    pfW<64, 64>(g_Wv2, sm + OFF_WA, tid);    // group 6

    const float scale = 0.35355339059327373f;   // 8^-0.5

    // ---- pan window attention: heads=8, dhead=4, seq=64 (512 rows / 2 iters) ----
    #pragma unroll
    for (int rr0 = 0; rr0 < 2; ++rr0) {
        int rr = tid + rr0 * TPB;
        int h = rr >> 6, i = rr & 63;
        const float* q = sm + OFF_PQ + i * LD32 + h * 4;
        float q0 = q[0] * scale, q1 = q[1] * scale, q2 = q[2] * scale, q3 = q[3] * scale;
        const float* piT = g_posT_inner + (h << 12) + i;
        float l = 0.f, o0 = 0.f, o1 = 0.f, o2 = 0.f, o3 = 0.f;
        #pragma unroll 4
        for (int j = 0; j < 64; ++j) {
            float4 kk = *(const float4*)(sm + OFF_PK + j * LD32 + h * 4);
            float s = q0 * kk.x + q1 * kk.y + q2 * kk.z + q3 * kk.w + piT[j << 6];
            float e = __expf(s);
            l += e;
            float4 vv = *(const float4*)(sm + OFF_V1 + j * LD64 + h * 4); // v1_pan cols 0..31
            o0 += e * vv.x; o1 += e * vv.y; o2 += e * vv.z; o3 += e * vv.w;
        }
        float inv = 1.f / l;
        float* oc = sm + OFF_X + i * LD64 + h * 4;   // cat cols [0,32)
        oc[0] = o0 * inv; oc[1] = o1 * inv; oc[2] = o2 * inv; oc[3] = o3 * inv;
    }

    // ---- color attention: heads=8, n=32 channels, d=8 tokens ----
    {
        int h = tid >> 5, i = tid & 31;
        float qd[8];
        #pragma unroll
        for (int d = 0; d < 8; ++d)
            qd[d] = sm[OFF_Q1 + (h * 8 + d) * LD32 + i] * scale;
        const float* pcT = g_posT_color + (h << 10) + i;
        float s[32];
        #pragma unroll
        for (int j = 0; j < 32; ++j)
            s[j] = pcT[j << 5];
        #pragma unroll
        for (int d = 0; d < 8; ++d) {
            const float* kr = sm + OFF_K1 + (h * 8 + d) * LD32;
            #pragma unroll
            for (int jc = 0; jc < 8; ++jc) {
                float4 k4 = *(const float4*)(kr + jc * 4);
                s[jc * 4 + 0] += qd[d] * k4.x;
                s[jc * 4 + 1] += qd[d] * k4.y;
                s[jc * 4 + 2] += qd[d] * k4.z;
                s[jc * 4 + 3] += qd[d] * k4.w;
            }
        }
        float l = 0.f;
        #pragma unroll
        for (int j = 0; j < 32; ++j) {
            s[j] = __expf(s[j]);
            l += s[j];
        }
        float o[8] = {0.f, 0.f, 0.f, 0.f, 0.f, 0.f, 0.f, 0.f};
        #pragma unroll
        for (int d = 0; d < 8; ++d) {
            const float* vr = sm + OFF_V1 + (h * 8 + d) * LD64 + 32;   // v1_color cols
            #pragma unroll
            for (int jc = 0; jc < 8; ++jc) {
                float4 v4 = *(const float4*)(vr + jc * 4);
                o[d] += s[jc * 4 + 0] * v4.x + s[jc * 4 + 1] * v4.y
                      + s[jc * 4 + 2] * v4.z + s[jc * 4 + 3] * v4.w;
            }
        }
        float inv = 1.f / l;
        #pragma unroll
        for (int d = 0; d < 8; ++d)
            sm[OFF_X + (h * 8 + d) * LD64 + 32 + i] = o[d] * inv;   // cat cols [32,64)
    }

    // ---- gemm5: out = cat @ Wio^T -> V1 ----
    CP_WAIT1(); __syncthreads();
    gemm<64, 64>(sm + OFF_X, sm + OFF_WB, sm + OFF_V1, tid);
    __syncthreads();
    pfW<32, 64>(g_Wk2, sm + OFF_WB, tid);    // group 7

    // ---- gemm6: v2 = out @ Wv2^T -> X ----
    CP_WAIT1(); __syncthreads();
    gemm<64, 64>(sm + OFF_V1, sm + OFF_WA, sm + OFF_X, tid);
    __syncthreads();
    pfW<64, 64>(g_Wto, sm + OFF_WA, tid);    // group 8

    // ---- gemm7: k2 = out @ Wk2^T -> K1 ----
    CP_WAIT1(); __syncthreads();
    gemm<32, 64>(sm + OFF_V1, sm + OFF_WB, sm + OFF_K1, tid);
    __syncthreads();

    // ---- cosine gate per (head, token) (512 / 2 iters) ----
    #pragma unroll
    for (int rr0 = 0; rr0 < 2; ++rr0) {
        int u = tid + rr0 * TPB;
        int h = u >> 6, t = u & 63;
        const float* q = sm + OFF_PQ + t * LD32 + h * 4;
        const float* k = sm + OFF_K1 + t * LD32 + h * 4;
        float dot = 0.f, qq = 0.f, kk = 0.f;
        #pragma unroll
        for (int d = 0; d < 4; ++d) {
            dot += q[d] * k[d];
            qq  += q[d] * q[d];
            kk  += k[d] * k[d];
        }
        sm[OFF_COS + h * 64 + t] = dot * rsqrtf(qq * kk);
    }
    __syncthreads();

    // ---- scale v2 in place: v2[t][c] *= cos[c>>3][t] ----
    #pragma unroll
    for (int r = 0; r < 16; ++r) {
        int e = tid + r * TPB;
        int t = e >> 6, c = e & 63;
        sm[OFF_X + t * LD64 + c] *= sm[OFF_COS + (c >> 3) * 64 + t];
    }

    // ---- gemm8: final = (cos*v2) @ Wto^T -> V1 ----
    CP_WAIT0(); __syncthreads();
    gemm<64, 64>(sm + OFF_X, sm + OFF_WA, sm + OFF_V1, tid);
    __syncthreads();

    // ---- un-partition and store ----
    #pragma unroll
    for (int r = 0; r < 16; ++r) {
        int e = tid + r * TPB;
        int c = e >> 6, t = e & 63;
        out[cbase + c * 65536 + (t >> 3) * 256 + (t & 7)] = sm[OFF_V1 + t * LD64 + c];
    }
}

extern "C" void kernel_launch(void* const* d_in, const int* in_sizes, int n_in,
                              void* d_out, int out_size)
{
    (void)in_sizes; (void)n_in; (void)out_size;

    prep_kernel<<<128, 256>>>(
        (const float*)d_in[11],  // pos_inner
        (const float*)d_in[12],  // pos_color
        (const float*)d_in[2],   // W_pan_q
        (const float*)d_in[3],   // W_pan_k
        (const float*)d_in[4],   // W_v1
        (const float*)d_in[5],   // W_v2
        (const float*)d_in[6],   // W_k2
        (const float*)d_in[7],   // W_q1c
        (const float*)d_in[8],   // W_k1c
        (const float*)d_in[9],   // W_inner_out
        (const float*)d_in[10]); // W_inter_out

    const size_t smem_bytes = SMEM_FLOATS * sizeof(float);       // 108,544 B
    cudaFuncSetAttribute(in2ma_kernel, cudaFuncAttributeMaxDynamicSharedMemorySize,
                         (int)smem_bytes);
    in2ma_kernel<<<4096, TPB, smem_bytes>>>(
        (const float*)d_in[0],  // x
        (const float*)d_in[1],  // pan_feature
        (float*)d_out);
}

// round 15
// speedup vs baseline: 3.8384x; 1.0934x over previous
#include <cuda_runtime.h>

typedef unsigned long long u64;

#define TPB 256

// ---------- tf32 helpers ----------
__device__ __forceinline__ unsigned cvt_tf32(float v) {
    unsigned r;
    asm("cvt.rna.tf32.f32 %0, %1;" : "=r"(r) : "f"(v));
    return r;
}
__device__ __forceinline__ float tf32_round(float v) {
    return __uint_as_float(cvt_tf32(v));
}
__device__ __forceinline__ void mma_tf32(float* c, const unsigned* a, const unsigned* b) {
    asm volatile(
        "mma.sync.aligned.m16n8k8.row.col.f32.tf32.tf32.f32 "
        "{%0,%1,%2,%3}, {%4,%5,%6,%7}, {%8,%9}, {%0,%1,%2,%3};"
        : "+f"(c[0]), "+f"(c[1]), "+f"(c[2]), "+f"(c[3])
        : "r"(a[0]), "r"(a[1]), "r"(a[2]), "r"(a[3]), "r"(b[0]), "r"(b[1]));
}
// ldmatrix x4 on 16B rows of fp32 data: 4 tf32-fragment regs in one LDSM.
__device__ __forceinline__ void ldsm_x4(unsigned* r, unsigned addr) {
    asm volatile("ldmatrix.sync.aligned.m8n8.x4.shared.b16 {%0,%1,%2,%3}, [%4];"
        : "=r"(r[0]), "=r"(r[1]), "=r"(r[2]), "=r"(r[3]) : "r"(addr));
}

// ---------- device scratch: pos tables + tf32-rounded weights ----------
// pos_inner stored pair-interleaved: [h][j][(i&31)*2 + (i>>5)] so a thread
// owning rows (h,i),(h,i+32) reads one float2.
__device__ float g_posT_inner[8 * 64 * 64];
__device__ float g_posT_color[8 * 32 * 32];
__device__ float g_Wpq [32 * 32];
__device__ float g_Wpk [32 * 32];
__device__ float g_Wv1 [64 * 64];
__device__ float g_Wv2 [64 * 64];
__device__ float g_Wk2 [32 * 64];
__device__ float g_Wq1c[32 * 64];
__device__ float g_Wk1c[32 * 64];
__device__ float g_Wio [64 * 64];
__device__ float g_Wto [64 * 64];

__global__ void prep_kernel(const float* __restrict__ pos_inner,
                            const float* __restrict__ pos_color,
                            const float* __restrict__ Wpq,  const float* __restrict__ Wpk,
                            const float* __restrict__ Wv1,  const float* __restrict__ Wv2,
                            const float* __restrict__ Wk2,  const float* __restrict__ Wq1c,
                            const float* __restrict__ Wk1c, const float* __restrict__ Wio,
                            const float* __restrict__ Wto)
{
    int t = blockIdx.x * blockDim.x + threadIdx.x;
    if (t < 8 * 64 * 64) {
        int h = t >> 12, i = (t >> 6) & 63, j = t & 63;   // src (h,i,j)
        g_posT_inner[(h << 12) | (j << 6) | ((i & 31) << 1) | (i >> 5)] = pos_inner[t];
    }
    if (t < 8 * 32 * 32) {
        int h = t >> 10, i = (t >> 5) & 31, j = t & 31;
        g_posT_color[(h << 10) | (j << 5) | i] = pos_color[t];
    }
    if (t < 1024) { g_Wpq[t] = tf32_round(Wpq[t]); g_Wpk[t] = tf32_round(Wpk[t]); }
    if (t < 2048) {
        g_Wk2[t]  = tf32_round(Wk2[t]);
        g_Wq1c[t] = tf32_round(Wq1c[t]);
        g_Wk1c[t] = tf32_round(Wk1c[t]);
    }
    if (t < 4096) {
        g_Wv1[t] = tf32_round(Wv1[t]);
        g_Wv2[t] = tf32_round(Wv2[t]);
        g_Wio[t] = tf32_round(Wio[t]);
        g_Wto[t] = tf32_round(Wto[t]);
    }
}

// ---------- shared memory layout (floats), 1 window / CTA, 2 CTAs / SM ----
#define LD64 68
#define LD32 36
#define OFF_X    0                       // 64x68: xf -> cat -> v2(scaled)
#define OFF_P    (OFF_X + 64*LD64)       // 64x36: pan, later q1c (pan dead by then)
#define OFF_PQ   (OFF_P + 64*LD32)       // 64x36: pan_q (kept until cos)
#define OFF_PK   (OFF_PQ + 64*LD32)      // 64x36: pan_k
#define OFF_V1   (OFF_PK + 64*LD32)      // 64x68: v1 -> inner-out -> final
#define OFF_Q1   OFF_P                   // alias: q1c reuses pan buffer
#define OFF_K1   (OFF_V1 + 64*LD64)      // 64x36: k1c -> k2
#define OFF_WA   (OFF_K1 + 64*LD32)      // 64x68: weight ping
#define OFF_WB   (OFF_WA + 64*LD64)      // 64x68: weight pong
#define OFF_COS  (OFF_WB + 64*LD64)      // 512:   cos[h][t]
#define SMEM_FLOATS (OFF_COS + 512)      // 27136 floats = 108544 B -> 2 CTAs/SM

// async weight prefetch: W[NO][KA] row-major (pre-rounded scratch) -> padded smem
template<int NO, int KA>
__device__ __forceinline__ void pfW(const float* __restrict__ g, float* __restrict__ s, int tid) {
    constexpr int LDW = KA + 4;
    constexpr int SH  = (KA == 64) ? 6 : 5;
    constexpr int CH  = (NO * KA) / (4 * TPB);
    #pragma unroll
    for (int r = 0; r < CH; ++r) {
        int q = (tid + r * TPB) * 4;
        int o = q >> SH, k = q & (KA - 1);
        unsigned sa = (unsigned)__cvta_generic_to_shared(s + o * LDW + k);
        asm volatile("cp.async.ca.shared.global [%0], [%1], 16;\n" :: "r"(sa), "l"(g + q));
    }
    asm volatile("cp.async.commit_group;\n");
}
#define CP_WAIT1() asm volatile("cp.async.wait_group 1;\n")
#define CP_WAIT0() asm volatile("cp.async.wait_group 0;\n")

// O[64][NO] = A[64][KA] @ W[NO][KA]^T  via split-A 2-term tf32 mma (fp32 accum),
// fragments loaded with ldmatrix.x4 (1 LDSM replaces 4 scalar LDS).
// 8 warps: warp (wid&3) owns M-rows [(wid&3)*16,+16); (wid>>2) owns N-half.
// Row pitches 68/36 floats == 16B mod 128B -> LDSM conflict-free.
template<int NO, int KA>
__device__ __forceinline__ void gemm(const float* __restrict__ A, const float* __restrict__ W,
                                     float* __restrict__ O, int tid)
{
    constexpr int LDA = KA + 4, LDW = KA + 4, LDO = NO + 4;
    constexpr int NB  = NO / 16;          // 8-wide n-blocks per warp
    constexpr int NP  = NB / 2;           // ldsm n-block pairs
    const int wid  = tid >> 5, lane = tid & 31;
    const int m0   = (wid & 3) * 16;
    const int n0   = (wid >> 2) * (NO / 2);
    const int gr   = lane >> 2, tg = lane & 3;
    const int lm   = lane & 7,  lq = lane >> 3;

    // A ldsm addressing: matrix0: rows m0+lm,   cols k0..3
    //                    matrix1: rows m0+8+lm, cols k0..3
    //                    matrix2: rows m0+lm,   cols k0+4..7
    //                    matrix3: rows m0+8+lm, cols k0+4..7
    const int arow = m0 + lm + ((lq & 1) << 3);
    const int acol = (lq >> 1) << 2;
    const unsigned aaddr = (unsigned)__cvta_generic_to_shared(A + arow * LDA + acol);
    // B ldsm addressing per pair p: matrices {b0(2p), b1(2p), b0(2p+1), b1(2p+1)}
    const int brow = n0 + ((lq >> 1) << 3) + lm;
    const int bcol = (lq & 1) << 2;
    const unsigned baddr = (unsigned)__cvta_generic_to_shared(W + brow * LDW + bcol);

    float acc[NB][4];
    #pragma unroll
    for (int nb = 0; nb < NB; ++nb)
        #pragma unroll
        for (int q = 0; q < 4; ++q) acc[nb][q] = 0.f;

    #pragma unroll
    for (int kb = 0; kb < KA / 8; ++kb) {
        unsigned av[4];
        ldsm_x4(av, aaddr + kb * 32);
        unsigned ahi[4], alo[4];
        #pragma unroll
        for (int q = 0; q < 4; ++q) {
            float f = __uint_as_float(av[q]);
            ahi[q] = cvt_tf32(f);
            alo[q] = cvt_tf32(f - __uint_as_float(ahi[q]));
        }
        #pragma unroll
        for (int p = 0; p < NP; ++p) {
            unsigned bv[4];
            ldsm_x4(bv, baddr + p * (16 * LDW * 4) + kb * 32);
            mma_tf32(acc[2 * p],     ahi, bv + 0);
            mma_tf32(acc[2 * p],     alo, bv + 0);
            mma_tf32(acc[2 * p + 1], ahi, bv + 2);
            mma_tf32(acc[2 * p + 1], alo, bv + 2);
        }
    }
    #pragma unroll
    for (int nb = 0; nb < NB; ++nb) {
        float* o0 = O + (m0 + gr) * LDO + n0 + nb * 8 + tg * 2;
        float* o1 = O + (m0 + 8 + gr) * LDO + n0 + nb * 8 + tg * 2;
        *(float2*)o0 = make_float2(acc[nb][0], acc[nb][1]);
        *(float2*)o1 = make_float2(acc[nb][2], acc[nb][3]);
    }
}

__global__ void __launch_bounds__(TPB, 2)
in2ma_kernel(const float* __restrict__ x, const float* __restrict__ pan,
             float* __restrict__ out)
{
    extern __shared__ float sm[];
    const int tid = threadIdx.x;
    const int wb  = blockIdx.x;
    const int b   = wb >> 10;
    const int hi  = (wb >> 5) & 31;
    const int wi  = wb & 31;

    const int cbase = (b * 64) * 65536 + (hi * 8) * 256 + wi * 8;
    const int pbase = (b * 32) * 65536 + (hi * 8) * 256 + wi * 8;

    // prefetch first two weights while staging activations
    pfW<32, 32>(g_Wpq, sm + OFF_WA, tid);    // group 0
    pfW<32, 32>(g_Wpk, sm + OFF_WB, tid);    // group 1

    // ---- stage window: xf[64tok][64ch], pan[64tok][32ch] ----
    #pragma unroll
    for (int r = 0; r < 16; ++r) {
        int e = tid + r * TPB;
        int c = e >> 6, t = e & 63;
        sm[OFF_X + t * LD64 + c] = x[cbase + c * 65536 + (t >> 3) * 256 + (t & 7)];
    }
    #pragma unroll
    for (int r = 0; r < 8; ++r) {
        int e = tid + r * TPB;
        int c = e >> 6, t = e & 63;
        sm[OFF_P + t * LD32 + c] = pan[pbase + c * 65536 + (t >> 3) * 256 + (t & 7)];
    }

    // ---- gemm0: pan_q = P @ Wpq^T -> PQ ----
    CP_WAIT1(); __syncthreads();
    gemm<32, 32>(sm + OFF_P, sm + OFF_WA, sm + OFF_PQ, tid);
    __syncthreads();
    pfW<64, 64>(g_Wv1, sm + OFF_WA, tid);    // group 2

    // ---- gemm1: pan_k = P @ Wpk^T -> PK ----
    CP_WAIT1(); __syncthreads();
    gemm<32, 32>(sm + OFF_P, sm + OFF_WB, sm + OFF_PK, tid);
    __syncthreads();
    pfW<32, 64>(g_Wq1c, sm + OFF_WB, tid);   // group 3

    // ---- gemm2: v1 = X @ Wv1^T -> V1 ----
    CP_WAIT1(); __syncthreads();
    gemm<64, 64>(sm + OFF_X, sm + OFF_WA, sm + OFF_V1, tid);
    __syncthreads();
    pfW<32, 64>(g_Wk1c, sm + OFF_WA, tid);   // group 4

    // ---- gemm3: q1c = X @ Wq1c^T -> Q1 (aliases P; pan is dead) ----
    CP_WAIT1(); __syncthreads();
    gemm<32, 64>(sm + OFF_X, sm + OFF_WB, sm + OFF_Q1, tid);
    __syncthreads();
    pfW<64, 64>(g_Wio, sm + OFF_WB, tid);    // group 5

    // ---- gemm4: k1c = X @ Wk1c^T -> K1 ----
    CP_WAIT1(); __syncthreads();
    gemm<32, 64>(sm + OFF_X, sm + OFF_WA, sm + OFF_K1, tid);
    __syncthreads();
    pfW<64, 64>(g_Wv2, sm + OFF_WA, tid);    // group 6

    const float scale = 0.35355339059327373f;   // 8^-0.5

    // ---- pan window attention: heads=8, dhead=4, seq=64 ----
    // thread owns rows (h,i) and (h,i+32): K/V loads shared between the two
    // rows (halves LDS issues); pos biases arrive as one float2 per j.
    {
        int h = tid >> 5, i = tid & 31;
        const float* qa = sm + OFF_PQ + i * LD32 + h * 4;
        const float* qb = sm + OFF_PQ + (i + 32) * LD32 + h * 4;
        float qa0 = qa[0] * scale, qa1 = qa[1] * scale, qa2 = qa[2] * scale, qa3 = qa[3] * scale;
        float qb0 = qb[0] * scale, qb1 = qb[1] * scale, qb2 = qb[2] * scale, qb3 = qb[3] * scale;
        const float2* ppT = (const float2*)(g_posT_inner + (h << 12)) + i;
        float la = 0.f, a0 = 0.f, a1 = 0.f, a2 = 0.f, a3 = 0.f;
        float lb = 0.f, b0 = 0.f, b1 = 0.f, b2 = 0.f, b3 = 0.f;
        #pragma unroll 4
        for (int j = 0; j < 64; ++j) {
            float4 kk = *(const float4*)(sm + OFF_PK + j * LD32 + h * 4);
            float2 pp = ppT[j << 5];
            float sa = qa0 * kk.x + qa1 * kk.y + qa2 * kk.z + qa3 * kk.w + pp.x;
            float sb = qb0 * kk.x + qb1 * kk.y + qb2 * kk.z + qb3 * kk.w + pp.y;
            float ea = __expf(sa);
            float eb = __expf(sb);
            la += ea; lb += eb;
            float4 vv = *(const float4*)(sm + OFF_V1 + j * LD64 + h * 4); // v1_pan cols 0..31
            a0 += ea * vv.x; a1 += ea * vv.y; a2 += ea * vv.z; a3 += ea * vv.w;
            b0 += eb * vv.x; b1 += eb * vv.y; b2 += eb * vv.z; b3 += eb * vv.w;
        }
        float ia = 1.f / la, ib = 1.f / lb;
        float* oa = sm + OFF_X + i * LD64 + h * 4;          // cat cols [0,32)
        float* ob = sm + OFF_X + (i + 32) * LD64 + h * 4;
        oa[0] = a0 * ia; oa[1] = a1 * ia; oa[2] = a2 * ia; oa[3] = a3 * ia;
        ob[0] = b0 * ib; ob[1] = b1 * ib; ob[2] = b2 * ib; ob[3] = b3 * ib;
    }

    // ---- color attention: heads=8, n=32 channels, d=8 tokens ----
    {
        int h = tid >> 5, i = tid & 31;
        float qd[8];
        #pragma unroll
        for (int d = 0; d < 8; ++d)
            qd[d] = sm[OFF_Q1 + (h * 8 + d) * LD32 + i] * scale;
        const float* pcT = g_posT_color + (h << 10) + i;
        float s[32];
        #pragma unroll
        for (int j = 0; j < 32; ++j)
            s[j] = pcT[j << 5];
        #pragma unroll
        for (int d = 0; d < 8; ++d) {
            const float* kr = sm + OFF_K1 + (h * 8 + d) * LD32;
            #pragma unroll
            for (int jc = 0; jc < 8; ++jc) {
                float4 k4 = *(const float4*)(kr + jc * 4);
                s[jc * 4 + 0] += qd[d] * k4.x;
                s[jc * 4 + 1] += qd[d] * k4.y;
                s[jc * 4 + 2] += qd[d] * k4.z;
                s[jc * 4 + 3] += qd[d] * k4.w;
            }
        }
        float l = 0.f;
        #pragma unroll
        for (int j = 0; j < 32; ++j) {
            s[j] = __expf(s[j]);
            l += s[j];
        }
        float o[8] = {0.f, 0.f, 0.f, 0.f, 0.f, 0.f, 0.f, 0.f};
        #pragma unroll
        for (int d = 0; d < 8; ++d) {
            const float* vr = sm + OFF_V1 + (h * 8 + d) * LD64 + 32;   // v1_color cols
            #pragma unroll
            for (int jc = 0; jc < 8; ++jc) {
                float4 v4 = *(const float4*)(vr + jc * 4);
                o[d] += s[jc * 4 + 0] * v4.x + s[jc * 4 + 1] * v4.y
                      + s[jc * 4 + 2] * v4.z + s[jc * 4 + 3] * v4.w;
            }
        }
        float inv = 1.f / l;
        #pragma unroll
        for (int d = 0; d < 8; ++d)
            sm[OFF_X + (h * 8 + d) * LD64 + 32 + i] = o[d] * inv;   // cat cols [32,64)
    }

    // ---- gemm5: out = cat @ Wio^T -> V1 ----
    CP_WAIT1(); __syncthreads();
    gemm<64, 64>(sm + OFF_X, sm + OFF_WB, sm + OFF_V1, tid);
    __syncthreads();
    pfW<32, 64>(g_Wk2, sm + OFF_WB, tid);    // group 7

    // ---- gemm6: v2 = out @ Wv2^T -> X ----
    CP_WAIT1(); __syncthreads();
    gemm<64, 64>(sm + OFF_V1, sm + OFF_WA, sm + OFF_X, tid);
    __syncthreads();
    pfW<64, 64>(g_Wto, sm + OFF_WA, tid);    // group 8

    // ---- gemm7: k2 = out @ Wk2^T -> K1 ----
    CP_WAIT1(); __syncthreads();
    gemm<32, 64>(sm + OFF_V1, sm + OFF_WB, sm + OFF_K1, tid);
    __syncthreads();

    // ---- cosine gate per (head, token) (512 / 2 iters) ----
    #pragma unroll
    for (int rr0 = 0; rr0 < 2; ++rr0) {
        int u = tid + rr0 * TPB;
        int h = u >> 6, t = u & 63;
        const float* q = sm + OFF_PQ + t * LD32 + h * 4;
        const float* k = sm + OFF_K1 + t * LD32 + h * 4;
        float dot = 0.f, qq = 0.f, kk = 0.f;
        #pragma unroll
        for (int d = 0; d < 4; ++d) {
            dot += q[d] * k[d];
            qq  += q[d] * q[d];
            kk  += k[d] * k[d];
        }
        sm[OFF_COS + h * 64 + t] = dot * rsqrtf(qq * kk);
    }
    __syncthreads();

    // ---- scale v2 in place: v2[t][c] *= cos[c>>3][t] ----
    #pragma unroll
    for (int r = 0; r < 16; ++r) {
        int e = tid + r * TPB;
        int t = e >> 6, c = e & 63;
        sm[OFF_X + t * LD64 + c] *= sm[OFF_COS + (c >> 3) * 64 + t];
    }

    // ---- gemm8: final = (cos*v2) @ Wto^T -> V1 ----
    CP_WAIT0(); __syncthreads();
    gemm<64, 64>(sm + OFF_X, sm + OFF_WA, sm + OFF_V1, tid);
    __syncthreads();

    // ---- un-partition and store ----
    #pragma unroll
    for (int r = 0; r < 16; ++r) {
        int e = tid + r * TPB;
        int c = e >> 6, t = e & 63;
        out[cbase + c * 65536 + (t >> 3) * 256 + (t & 7)] = sm[OFF_V1 + t * LD64 + c];
    }
}

extern "C" void kernel_launch(void* const* d_in, const int* in_sizes, int n_in,
                              void* d_out, int out_size)
{
    (void)in_sizes; (void)n_in; (void)out_size;

    prep_kernel<<<128, 256>>>(
        (const float*)d_in[11],  // pos_inner
        (const float*)d_in[12],  // pos_color
        (const float*)d_in[2],   // W_pan_q
        (const float*)d_in[3],   // W_pan_k
        (const float*)d_in[4],   // W_v1
        (const float*)d_in[5],   // W_v2
        (const float*)d_in[6],   // W_k2
        (const float*)d_in[7],   // W_q1c
        (const float*)d_in[8],   // W_k1c
        (const float*)d_in[9],   // W_inner_out
        (const float*)d_in[10]); // W_inter_out

    const size_t smem_bytes = SMEM_FLOATS * sizeof(float);       // 108,544 B
    cudaFuncSetAttribute(in2ma_kernel, cudaFuncAttributeMaxDynamicSharedMemorySize,
                         (int)smem_bytes);
    in2ma_kernel<<<4096, TPB, smem_bytes>>>(
        (const float*)d_in[0],  // x
        (const float*)d_in[1],  // pan_feature
        (float*)d_out);
}